// round 1
// baseline (speedup 1.0000x reference)
#include <cuda_runtime.h>

#define D_MODEL  1024
#define N_HEADS  16
#define HEAD_DIM 64
#define BATCH    2
#define SEQ      2048
#define M_TOTAL  (BATCH * SEQ)   // 4096

// Scratch (device globals: allocation-free rule)
__device__ float g_Q[BATCH * N_HEADS * SEQ * HEAD_DIM];   // [B,H,S,Hd]
__device__ float g_K[BATCH * N_HEADS * SEQ * HEAD_DIM];
__device__ float g_V[BATCH * N_HEADS * SEQ * HEAD_DIM];
__device__ float g_O[M_TOTAL * D_MODEL];                  // [B,S,D]

// ---------------------------------------------------------------------------
// SGEMM with bias: C = (A[M,K] @ W[K,N] + bias) * scale
// qkv_mode==1 : scatter into [B,H,S,Hd] layout
// qkv_mode==0 : plain row-major [M,N]
// Tile: BM=64, BN=64, BK=16, 256 threads, 4x4 per-thread micro-tile.
// ---------------------------------------------------------------------------
#define BM 64
#define BN 64
#define BK 16

__global__ __launch_bounds__(256) void sgemm_bias(
    const float* __restrict__ A, const float* __restrict__ W,
    const float* __restrict__ bias, float* __restrict__ C,
    float scale, int qkv_mode)
{
    const int K = D_MODEL, N = D_MODEL;
    // +4 pad keeps rows 272B (16B-aligned) and kills smem bank conflicts
    __shared__ float As[BK][BM + 4];
    __shared__ float Bs[BK][BN + 4];

    const int tid = threadIdx.x;
    const int m0 = blockIdx.y * BM;
    const int n0 = blockIdx.x * BN;
    const int tx = tid & 15;       // 0..15 (n)
    const int ty = tid >> 4;       // 0..15 (m)

    // A-tile load map: one float4 along k per thread
    const int am = tid >> 2;              // 0..63 (m within tile)
    const int ak = (tid & 3) * 4;         // 0,4,8,12 (k within tile)
    // B-tile load map: scalar, fully coalesced
    const int bkr = tid >> 6;             // 0..3
    const int bn  = tid & 63;             // 0..63

    float acc[4][4];
    #pragma unroll
    for (int i = 0; i < 4; ++i)
        #pragma unroll
        for (int j = 0; j < 4; ++j) acc[i][j] = 0.f;

    for (int k0 = 0; k0 < K; k0 += BK) {
        float4 a4 = *(const float4*)(&A[(m0 + am) * K + k0 + ak]);
        As[ak + 0][am] = a4.x;
        As[ak + 1][am] = a4.y;
        As[ak + 2][am] = a4.z;
        As[ak + 3][am] = a4.w;
        #pragma unroll
        for (int p = 0; p < 4; ++p) {
            int kl = p * 4 + bkr;
            Bs[kl][bn] = W[(k0 + kl) * N + n0 + bn];
        }
        __syncthreads();

        #pragma unroll
        for (int k = 0; k < BK; ++k) {
            float4 ra = *(const float4*)(&As[k][ty * 4]);
            float4 rb = *(const float4*)(&Bs[k][tx * 4]);
            float av[4] = {ra.x, ra.y, ra.z, ra.w};
            float bv[4] = {rb.x, rb.y, rb.z, rb.w};
            #pragma unroll
            for (int i = 0; i < 4; ++i)
                #pragma unroll
                for (int j = 0; j < 4; ++j)
                    acc[i][j] += av[i] * bv[j];
        }
        __syncthreads();
    }

    #pragma unroll
    for (int i = 0; i < 4; ++i) {
        int m = m0 + ty * 4 + i;
        int b = m >> 11;           // /SEQ
        int s = m & (SEQ - 1);
        #pragma unroll
        for (int j = 0; j < 4; ++j) {
            int n = n0 + tx * 4 + j;
            float v = (acc[i][j] + bias[n]) * scale;
            if (qkv_mode) {
                int h = n >> 6, hd = n & 63;
                C[(((b * N_HEADS + h) * SEQ) + s) * HEAD_DIM + hd] = v;
            } else {
                C[m * N + n] = v;
            }
        }
    }
}

// ---------------------------------------------------------------------------
// Causal flash attention, fp32, Q pre-scaled by 1/sqrt(Hd).
// One (b,h) per blockIdx.y, 64 query rows per CTA, one row per thread.
// K/V tiles staged in padded smem; online softmax per key.
// ---------------------------------------------------------------------------
__global__ __launch_bounds__(64) void flash_attn(
    const float* __restrict__ Qg, const float* __restrict__ Kg,
    const float* __restrict__ Vg, float* __restrict__ Og)
{
    __shared__ float Ks[64][68];
    __shared__ float Vs[64][68];

    const int tid = threadIdx.x;
    const int bh  = blockIdx.y;          // 0..31
    const int q0  = blockIdx.x * 64;
    const int qi  = q0 + tid;
    const int base = bh * SEQ * HEAD_DIM;

    // q row -> registers
    float q[64];
    #pragma unroll
    for (int d4 = 0; d4 < 16; ++d4) {
        float4 t = *(const float4*)(&Qg[base + qi * 64 + d4 * 4]);
        q[d4 * 4 + 0] = t.x; q[d4 * 4 + 1] = t.y;
        q[d4 * 4 + 2] = t.z; q[d4 * 4 + 3] = t.w;
    }

    float acc[64];
    #pragma unroll
    for (int d = 0; d < 64; ++d) acc[d] = 0.f;
    float mi = -1e30f, li = 0.f;

    for (int k0 = 0; k0 <= q0; k0 += 64) {
        // stage K/V tile: one row per thread, float4
        #pragma unroll
        for (int d4 = 0; d4 < 16; ++d4) {
            *(float4*)(&Ks[tid][d4 * 4]) =
                *(const float4*)(&Kg[base + (k0 + tid) * 64 + d4 * 4]);
            *(float4*)(&Vs[tid][d4 * 4]) =
                *(const float4*)(&Vg[base + (k0 + tid) * 64 + d4 * 4]);
        }
        __syncthreads();

        const int tmax = (k0 == q0) ? (tid + 1) : 64;  // causal diagonal
        for (int t = 0; t < tmax; ++t) {
            float s0 = 0.f, s1 = 0.f, s2 = 0.f, s3 = 0.f;
            #pragma unroll
            for (int d = 0; d < 64; d += 4) {
                s0 += q[d + 0] * Ks[t][d + 0];
                s1 += q[d + 1] * Ks[t][d + 1];
                s2 += q[d + 2] * Ks[t][d + 2];
                s3 += q[d + 3] * Ks[t][d + 3];
            }
            float s = (s0 + s1) + (s2 + s3);      // already /sqrt(Hd) via Q scale
            float mnew = fmaxf(mi, s);
            float p    = __expf(s - mnew);
            float corr = __expf(mi - mnew);
            li = li * corr + p;
            mi = mnew;
            #pragma unroll
            for (int d = 0; d < 64; ++d)
                acc[d] = acc[d] * corr + p * Vs[t][d];
        }
        __syncthreads();
    }

    // write O in [B,S,D] layout so final GEMM reads it row-major
    const int b = bh >> 4, h = bh & 15;
    const float inv = 1.f / li;
    const int obase = (b * SEQ + qi) * D_MODEL + h * HEAD_DIM;
    #pragma unroll
    for (int d4 = 0; d4 < 16; ++d4) {
        float4 o;
        o.x = acc[d4 * 4 + 0] * inv;
        o.y = acc[d4 * 4 + 1] * inv;
        o.z = acc[d4 * 4 + 2] * inv;
        o.w = acc[d4 * 4 + 3] * inv;
        *(float4*)(&Og[obase + d4 * 4]) = o;
    }
}

// ---------------------------------------------------------------------------
extern "C" void kernel_launch(void* const* d_in, const int* in_sizes, int n_in,
                              void* d_out, int out_size)
{
    (void)in_sizes; (void)n_in; (void)out_size;
    const float* x  = (const float*)d_in[0];
    const float* Wq = (const float*)d_in[1];
    const float* bq = (const float*)d_in[2];
    const float* Wk = (const float*)d_in[3];
    const float* bk = (const float*)d_in[4];
    const float* Wv = (const float*)d_in[5];
    const float* bv = (const float*)d_in[6];
    const float* Wo = (const float*)d_in[7];
    const float* bo = (const float*)d_in[8];
    float* out = (float*)d_out;

    float *Q, *K, *V, *O;
    cudaGetSymbolAddress((void**)&Q, g_Q);
    cudaGetSymbolAddress((void**)&K, g_K);
    cudaGetSymbolAddress((void**)&V, g_V);
    cudaGetSymbolAddress((void**)&O, g_O);

    dim3 gg(D_MODEL / BN, M_TOTAL / BM);   // (16, 64)
    dim3 ga(SEQ / 64, BATCH * N_HEADS);    // (32, 32)

    sgemm_bias<<<gg, 256>>>(x, Wq, bq, Q, 0.125f, 1);  // 1/sqrt(64) folded into Q
    sgemm_bias<<<gg, 256>>>(x, Wk, bk, K, 1.0f, 1);
    sgemm_bias<<<gg, 256>>>(x, Wv, bv, V, 1.0f, 1);
    flash_attn<<<ga, 64>>>(Q, K, V, O);
    sgemm_bias<<<gg, 256>>>(O, Wo, bo, out, 1.0f, 0);
}

// round 3
// speedup vs baseline: 1.5069x; 1.5069x over previous
#include <cuda_runtime.h>
#include <cuda_bf16.h>
#include <cstdint>

#define D_MODEL  1024
#define N_HEADS  16
#define HEAD_DIM 64
#define BATCH    2
#define SEQ      2048
#define M_TOTAL  (BATCH * SEQ)   // 4096

// ---------------------------------------------------------------------------
// Device-global scratch (allocation-free rule)
// ---------------------------------------------------------------------------
__device__ __align__(16) float g_Q[BATCH * N_HEADS * SEQ * HEAD_DIM];
__device__ __align__(16) float g_K[BATCH * N_HEADS * SEQ * HEAD_DIM];
__device__ __align__(16) float g_V[BATCH * N_HEADS * SEQ * HEAD_DIM];
__device__ __align__(16) __nv_bfloat16 g_xh[M_TOTAL * D_MODEL];
__device__ __align__(16) __nv_bfloat16 g_xl[M_TOTAL * D_MODEL];
__device__ __align__(16) __nv_bfloat16 g_Wth[4 * D_MODEL * D_MODEL]; // W^T hi [N,K]
__device__ __align__(16) __nv_bfloat16 g_Wtl[4 * D_MODEL * D_MODEL]; // W^T lo [N,K]
__device__ __align__(16) __nv_bfloat16 g_Oh[M_TOTAL * D_MODEL];
__device__ __align__(16) __nv_bfloat16 g_Ol[M_TOTAL * D_MODEL];

// ---------------------------------------------------------------------------
// mma.sync / ldmatrix helpers (compute_103-legal, runs on tensor pipe)
// ---------------------------------------------------------------------------
__device__ __forceinline__ uint32_t smem_u32(const void* p) {
    uint32_t a;
    asm("{ .reg .u64 t; cvta.to.shared.u64 t, %1; cvt.u32.u64 %0, t; }"
        : "=r"(a) : "l"(p));
    return a;
}

__device__ __forceinline__ void ldsm4(uint32_t* r, uint32_t addr) {
    asm volatile("ldmatrix.sync.aligned.m8n8.x4.shared.b16 {%0,%1,%2,%3}, [%4];"
        : "=r"(r[0]), "=r"(r[1]), "=r"(r[2]), "=r"(r[3]) : "r"(addr));
}

__device__ __forceinline__ void mma_bf16(float* c, const uint32_t* a,
                                         uint32_t b0, uint32_t b1) {
    asm volatile(
        "mma.sync.aligned.m16n8k16.row.col.f32.bf16.bf16.f32 "
        "{%0,%1,%2,%3}, {%4,%5,%6,%7}, {%8,%9}, {%0,%1,%2,%3};"
        : "+f"(c[0]), "+f"(c[1]), "+f"(c[2]), "+f"(c[3])
        : "r"(a[0]), "r"(a[1]), "r"(a[2]), "r"(a[3]), "r"(b0), "r"(b1));
}

// ---------------------------------------------------------------------------
// fp32 -> (bf16 hi, bf16 lo) split, float4-vectorized
// ---------------------------------------------------------------------------
__global__ __launch_bounds__(256) void convert_split(
    const float* __restrict__ X, __nv_bfloat16* __restrict__ H,
    __nv_bfloat16* __restrict__ L, int n4)
{
    int i = blockIdx.x * blockDim.x + threadIdx.x;
    if (i >= n4) return;
    float4 v = ((const float4*)X)[i];
    __nv_bfloat16 hv[4], lv[4];
    float f[4] = {v.x, v.y, v.z, v.w};
    #pragma unroll
    for (int e = 0; e < 4; ++e) {
        hv[e] = __float2bfloat16_rn(f[e]);
        lv[e] = __float2bfloat16_rn(f[e] - __bfloat162float(hv[e]));
    }
    ((uint2*)H)[i] = *(const uint2*)hv;
    ((uint2*)L)[i] = *(const uint2*)lv;
}

// ---------------------------------------------------------------------------
// W [K,N] fp32 -> W^T [N,K] bf16 hi/lo (32x32 smem transpose)
// ---------------------------------------------------------------------------
__global__ __launch_bounds__(256) void wtrans_split(
    const float* __restrict__ W, __nv_bfloat16* __restrict__ Th,
    __nv_bfloat16* __restrict__ Tl)
{
    __shared__ float t[32][33];
    const int bx = blockIdx.x * 32;   // n block
    const int by = blockIdx.y * 32;   // k block
    const int x = threadIdx.x, y = threadIdx.y;
    #pragma unroll
    for (int j = 0; j < 32; j += 8)
        t[y + j][x] = W[(by + y + j) * D_MODEL + bx + x];
    __syncthreads();
    #pragma unroll
    for (int j = 0; j < 32; j += 8) {
        float v = t[x][y + j];                 // (k=by+x, n=bx+y+j)
        __nv_bfloat16 h = __float2bfloat16_rn(v);
        __nv_bfloat16 l = __float2bfloat16_rn(v - __bfloat162float(h));
        Th[(bx + y + j) * D_MODEL + by + x] = h;
        Tl[(bx + y + j) * D_MODEL + by + x] = l;
    }
}

// ---------------------------------------------------------------------------
// bf16x3-split GEMM via mma.sync:  C[M,N] = (A @ W + bias) * scale
//   A = (Ah,Al) bf16 [M,K] row-major;  W^T = (Bh,Bl) bf16 [N,K] row-major
//   C ≈ Ah*Bh + Al*Bh + Ah*Bl, fp32 accumulate.
// CTA tile 128x128, K-chunk 32, 8 warps (2x4), warp tile 64x32.
// Smem rows padded to 80B (20 words): conflict-free ldmatrix.
// ---------------------------------------------------------------------------
#define GK     32
#define NKCH   (D_MODEL / GK)        // 32
#define ROW_B  80                    // padded bytes per 32-bf16 row
#define TILE_B (128 * ROW_B)         // 10240 bytes
#define STG_B  (4 * TILE_B)          // Ah, Al, Bh, Bl = 40960
#define GEMM_SMEM (2 * STG_B)        // 81920

__global__ __launch_bounds__(256, 1)
void gemm_mma(const __nv_bfloat16* __restrict__ Ah,
              const __nv_bfloat16* __restrict__ Al,
              const __nv_bfloat16* __restrict__ Bh,
              const __nv_bfloat16* __restrict__ Bl,
              const float* __restrict__ bias,
              float* __restrict__ C, float scale, int qkv_mode)
{
    extern __shared__ char smem[];
    const uint32_t sb = smem_u32(smem);
    const int tid  = threadIdx.x;
    const int lane = tid & 31;
    const int wid  = tid >> 5;
    const int m0 = blockIdx.y * 128;
    const int n0 = blockIdx.x * 128;
    const int wm = (wid & 1) * 64;     // warp m offset in tile
    const int wn = (wid >> 1) * 32;    // warp n offset in tile

    // gmem->smem load map: 2 threads per 32-bf16 row, 2x16B chunks each
    const int lrow = tid >> 1;          // 0..127
    const int lhalf = tid & 1;          // chunk base: lhalf*2
    const __nv_bfloat16* pAh = Ah + (size_t)(m0 + lrow) * D_MODEL;
    const __nv_bfloat16* pAl = Al + (size_t)(m0 + lrow) * D_MODEL;
    const __nv_bfloat16* pBh = Bh + (size_t)(n0 + lrow) * D_MODEL;
    const __nv_bfloat16* pBl = Bl + (size_t)(n0 + lrow) * D_MODEL;
    const uint32_t w0 = (uint32_t)lrow * ROW_B + (uint32_t)(lhalf * 2) * 16u;
    const uint32_t w1 = w0 + 16u;

    // ldmatrix per-thread base offsets
    const uint32_t a_off = (uint32_t)(wm + (lane & 15)) * ROW_B
                         + (uint32_t)(lane >> 4) * 16u;
    const uint32_t b_off = (uint32_t)(wn + ((lane >> 4) << 3) + (lane & 7)) * ROW_B
                         + (uint32_t)((lane >> 3) & 1) * 16u;

    float acc[4][4][4];
    #pragma unroll
    for (int i = 0; i < 4; ++i)
        #pragma unroll
        for (int j = 0; j < 4; ++j)
            #pragma unroll
            for (int r = 0; r < 4; ++r) acc[i][j][r] = 0.f;

    uint4 rA_h[2], rA_l[2], rB_h[2], rB_l[2];
    // preload chunk 0
    {
        const int e0 = lhalf * 16;      // element offset of chunk pair
        rA_h[0] = *(const uint4*)(pAh + e0);     rA_h[1] = *(const uint4*)(pAh + e0 + 8);
        rA_l[0] = *(const uint4*)(pAl + e0);     rA_l[1] = *(const uint4*)(pAl + e0 + 8);
        rB_h[0] = *(const uint4*)(pBh + e0);     rB_h[1] = *(const uint4*)(pBh + e0 + 8);
        rB_l[0] = *(const uint4*)(pBl + e0);     rB_l[1] = *(const uint4*)(pBl + e0 + 8);
        char* s = smem;                          // stage 0
        *(uint4*)(s + w0) = rA_h[0];             *(uint4*)(s + w1) = rA_h[1];
        *(uint4*)(s + TILE_B + w0) = rA_l[0];    *(uint4*)(s + TILE_B + w1) = rA_l[1];
        *(uint4*)(s + 2*TILE_B + w0) = rB_h[0];  *(uint4*)(s + 2*TILE_B + w1) = rB_h[1];
        *(uint4*)(s + 3*TILE_B + w0) = rB_l[0];  *(uint4*)(s + 3*TILE_B + w1) = rB_l[1];
    }

    for (int i = 0; i < NKCH; ++i) {
        // prefetch next chunk into registers
        if (i + 1 < NKCH) {
            const int e = (i + 1) * GK + lhalf * 16;
            rA_h[0] = *(const uint4*)(pAh + e);     rA_h[1] = *(const uint4*)(pAh + e + 8);
            rA_l[0] = *(const uint4*)(pAl + e);     rA_l[1] = *(const uint4*)(pAl + e + 8);
            rB_h[0] = *(const uint4*)(pBh + e);     rB_h[1] = *(const uint4*)(pBh + e + 8);
            rB_l[0] = *(const uint4*)(pBl + e);     rB_l[1] = *(const uint4*)(pBl + e + 8);
        }
        __syncthreads();   // smem stage (i&1) fully written

        const uint32_t stg = sb + (uint32_t)(i & 1) * STG_B;
        #pragma unroll
        for (int ks = 0; ks < 2; ++ks) {
            uint32_t ah[4][4], al[4][4], bh[2][4], bl[2][4];
            #pragma unroll
            for (int mt = 0; mt < 4; ++mt) {
                ldsm4(ah[mt], stg + a_off + mt * (16 * ROW_B) + ks * 32);
                ldsm4(al[mt], stg + TILE_B + a_off + mt * (16 * ROW_B) + ks * 32);
            }
            #pragma unroll
            for (int ng = 0; ng < 2; ++ng) {
                ldsm4(bh[ng], stg + 2 * TILE_B + b_off + ng * (16 * ROW_B) + ks * 32);
                ldsm4(bl[ng], stg + 3 * TILE_B + b_off + ng * (16 * ROW_B) + ks * 32);
            }
            #pragma unroll
            for (int mt = 0; mt < 4; ++mt)
                #pragma unroll
                for (int n8 = 0; n8 < 4; ++n8) {
                    const int ng = n8 >> 1, hf = (n8 & 1) * 2;
                    mma_bf16(acc[mt][n8], ah[mt], bh[ng][hf], bh[ng][hf + 1]);
                    mma_bf16(acc[mt][n8], al[mt], bh[ng][hf], bh[ng][hf + 1]);
                    mma_bf16(acc[mt][n8], ah[mt], bl[ng][hf], bl[ng][hf + 1]);
                }
        }

        if (i + 1 < NKCH) {
            __syncthreads();   // all warps done reading stage ((i+1)&1)'s old data
            char* s = smem + ((i + 1) & 1) * STG_B;
            *(uint4*)(s + w0) = rA_h[0];             *(uint4*)(s + w1) = rA_h[1];
            *(uint4*)(s + TILE_B + w0) = rA_l[0];    *(uint4*)(s + TILE_B + w1) = rA_l[1];
            *(uint4*)(s + 2*TILE_B + w0) = rB_h[0];  *(uint4*)(s + 2*TILE_B + w1) = rB_h[1];
            *(uint4*)(s + 3*TILE_B + w0) = rB_l[0];  *(uint4*)(s + 3*TILE_B + w1) = rB_l[1];
        }
    }

    // epilogue: bias + scale, optional scatter to [B,H,S,Hd]
    const int mrow = lane >> 2;
    const int ncol = (lane & 3) * 2;
    #pragma unroll
    for (int mt = 0; mt < 4; ++mt) {
        #pragma unroll
        for (int n8 = 0; n8 < 4; ++n8) {
            const int n = n0 + wn + n8 * 8 + ncol;
            const float bx = bias[n], by = bias[n + 1];
            #pragma unroll
            for (int h2 = 0; h2 < 2; ++h2) {
                const int m = m0 + wm + mt * 16 + mrow + h2 * 8;
                float2 v;
                v.x = (acc[mt][n8][h2 * 2 + 0] + bx) * scale;
                v.y = (acc[mt][n8][h2 * 2 + 1] + by) * scale;
                const int b = m >> 11, s = m & (SEQ - 1);
                if (qkv_mode) {
                    const int hh = n >> 6, hd = n & 63;
                    *(float2*)&C[(((size_t)(b * N_HEADS + hh) * SEQ) + s) * HEAD_DIM + hd] = v;
                } else {
                    *(float2*)&C[(size_t)m * D_MODEL + n] = v;
                }
            }
        }
    }
}

// ---------------------------------------------------------------------------
// Causal flash attention, fp32 SIMT; Q pre-scaled by 1/sqrt(Hd).
// Branch-on-new-max rescale; writes O as bf16 hi/lo in [B,S,D].
// ---------------------------------------------------------------------------
__global__ __launch_bounds__(64) void flash_attn(
    const float* __restrict__ Qg, const float* __restrict__ Kg,
    const float* __restrict__ Vg, __nv_bfloat16* __restrict__ Oh,
    __nv_bfloat16* __restrict__ Ol)
{
    __shared__ float Ks[64][68];
    __shared__ float Vs[64][68];

    const int tid = threadIdx.x;
    const int bh  = blockIdx.y;
    const int q0  = (gridDim.x - 1 - blockIdx.x) * 64;  // long blocks first
    const int qi  = q0 + tid;
    const int base = bh * SEQ * HEAD_DIM;

    float q[64];
    #pragma unroll
    for (int d4 = 0; d4 < 16; ++d4) {
        float4 t = *(const float4*)(&Qg[base + qi * 64 + d4 * 4]);
        q[d4 * 4 + 0] = t.x; q[d4 * 4 + 1] = t.y;
        q[d4 * 4 + 2] = t.z; q[d4 * 4 + 3] = t.w;
    }

    float acc[64];
    #pragma unroll
    for (int d = 0; d < 64; ++d) acc[d] = 0.f;
    float mi = -1e30f, li = 0.f;

    for (int k0 = 0; k0 <= q0; k0 += 64) {
        #pragma unroll
        for (int d4 = 0; d4 < 16; ++d4) {
            *(float4*)(&Ks[tid][d4 * 4]) =
                *(const float4*)(&Kg[base + (k0 + tid) * 64 + d4 * 4]);
            *(float4*)(&Vs[tid][d4 * 4]) =
                *(const float4*)(&Vg[base + (k0 + tid) * 64 + d4 * 4]);
        }
        __syncthreads();

        const int tmax = (k0 == q0) ? (tid + 1) : 64;
        for (int t = 0; t < tmax; ++t) {
            float s0 = 0.f, s1 = 0.f, s2 = 0.f, s3 = 0.f;
            #pragma unroll
            for (int d = 0; d < 64; d += 4) {
                s0 += q[d + 0] * Ks[t][d + 0];
                s1 += q[d + 1] * Ks[t][d + 1];
                s2 += q[d + 2] * Ks[t][d + 2];
                s3 += q[d + 3] * Ks[t][d + 3];
            }
            const float s = (s0 + s1) + (s2 + s3);
            float p;
            if (s > mi) {                       // rare after warmup
                const float corr = __expf(mi - s);
                li *= corr;
                #pragma unroll
                for (int d = 0; d < 64; ++d) acc[d] *= corr;
                mi = s;
                p = 1.f;
            } else {
                p = __expf(s - mi);
            }
            li += p;
            #pragma unroll
            for (int d = 0; d < 64; ++d)
                acc[d] += p * Vs[t][d];
        }
        __syncthreads();
    }

    const int b = bh >> 4, h = bh & 15;
    const float inv = 1.f / li;
    const size_t obase = ((size_t)(b * SEQ + qi)) * D_MODEL + h * HEAD_DIM;
    #pragma unroll
    for (int d4 = 0; d4 < 16; ++d4) {
        __nv_bfloat16 hv[4], lv[4];
        #pragma unroll
        for (int e = 0; e < 4; ++e) {
            float o = acc[d4 * 4 + e] * inv;
            hv[e] = __float2bfloat16_rn(o);
            lv[e] = __float2bfloat16_rn(o - __bfloat162float(hv[e]));
        }
        *(uint2*)(&Oh[obase + d4 * 4]) = *(const uint2*)hv;
        *(uint2*)(&Ol[obase + d4 * 4]) = *(const uint2*)lv;
    }
}

// ---------------------------------------------------------------------------
extern "C" void kernel_launch(void* const* d_in, const int* in_sizes, int n_in,
                              void* d_out, int out_size)
{
    (void)in_sizes; (void)n_in; (void)out_size;
    const float* x  = (const float*)d_in[0];
    const float* Wq = (const float*)d_in[1];
    const float* bq = (const float*)d_in[2];
    const float* Wk = (const float*)d_in[3];
    const float* bk = (const float*)d_in[4];
    const float* Wv = (const float*)d_in[5];
    const float* bv = (const float*)d_in[6];
    const float* Wo = (const float*)d_in[7];
    const float* bo = (const float*)d_in[8];
    float* out = (float*)d_out;

    float *Q, *K, *V;
    __nv_bfloat16 *xh, *xl, *Wth, *Wtl, *Oh, *Ol;
    cudaGetSymbolAddress((void**)&Q,   g_Q);
    cudaGetSymbolAddress((void**)&K,   g_K);
    cudaGetSymbolAddress((void**)&V,   g_V);
    cudaGetSymbolAddress((void**)&xh,  g_xh);
    cudaGetSymbolAddress((void**)&xl,  g_xl);
    cudaGetSymbolAddress((void**)&Wth, g_Wth);
    cudaGetSymbolAddress((void**)&Wtl, g_Wtl);
    cudaGetSymbolAddress((void**)&Oh,  g_Oh);
    cudaGetSymbolAddress((void**)&Ol,  g_Ol);

    cudaFuncSetAttribute(gemm_mma,
                         cudaFuncAttributeMaxDynamicSharedMemorySize, GEMM_SMEM);

    const size_t WSZ = (size_t)D_MODEL * D_MODEL;

    // 1) split x into bf16 hi/lo
    convert_split<<<(M_TOTAL * D_MODEL / 4 + 255) / 256, 256>>>(
        x, xh, xl, M_TOTAL * D_MODEL / 4);

    // 2) transpose+split weights
    dim3 wtg(32, 32), wtb(32, 8);
    wtrans_split<<<wtg, wtb>>>(Wq, Wth + 0 * WSZ, Wtl + 0 * WSZ);
    wtrans_split<<<wtg, wtb>>>(Wk, Wth + 1 * WSZ, Wtl + 1 * WSZ);
    wtrans_split<<<wtg, wtb>>>(Wv, Wth + 2 * WSZ, Wtl + 2 * WSZ);
    wtrans_split<<<wtg, wtb>>>(Wo, Wth + 3 * WSZ, Wtl + 3 * WSZ);

    // 3) Q/K/V projections (mma.sync), scatter to [B,H,S,Hd]; 1/8 folded into Q
    dim3 gg(D_MODEL / 128, M_TOTAL / 128);   // (8, 32)
    gemm_mma<<<gg, 256, GEMM_SMEM>>>(xh, xl, Wth + 0 * WSZ, Wtl + 0 * WSZ,
                                     bq, Q, 0.125f, 1);
    gemm_mma<<<gg, 256, GEMM_SMEM>>>(xh, xl, Wth + 1 * WSZ, Wtl + 1 * WSZ,
                                     bk, K, 1.0f, 1);
    gemm_mma<<<gg, 256, GEMM_SMEM>>>(xh, xl, Wth + 2 * WSZ, Wtl + 2 * WSZ,
                                     bv, V, 1.0f, 1);

    // 4) causal flash attention -> O (bf16 hi/lo, [B,S,D])
    dim3 ga(SEQ / 64, BATCH * N_HEADS);
    flash_attn<<<ga, 64>>>(Q, K, V, Oh, Ol);

    // 5) output projection (mma.sync) -> d_out fp32
    gemm_mma<<<gg, 256, GEMM_SMEM>>>(Oh, Ol, Wth + 3 * WSZ, Wtl + 3 * WSZ,
                                     bo, out, 1.0f, 0);
}

// round 4
// speedup vs baseline: 3.3406x; 2.2168x over previous
#include <cuda_runtime.h>
#include <cuda_bf16.h>
#include <cstdint>

#define D_MODEL  1024
#define N_HEADS  16
#define HEAD_DIM 64
#define BATCH    2
#define SEQ      2048
#define M_TOTAL  (BATCH * SEQ)   // 4096
#define QSCALE   0.18033688011112042f   // 0.125 * log2(e)

// ---------------------------------------------------------------------------
// Device-global scratch (allocation-free rule)
// ---------------------------------------------------------------------------
#define PHSZ (BATCH * N_HEADS * SEQ * HEAD_DIM)   // 4M elems
__device__ __align__(16) __nv_bfloat16 g_Qh[PHSZ], g_Ql[PHSZ];
__device__ __align__(16) __nv_bfloat16 g_Kh[PHSZ], g_Kl[PHSZ];
__device__ __align__(16) __nv_bfloat16 g_Vh[PHSZ], g_Vl[PHSZ];
__device__ __align__(16) __nv_bfloat16 g_xh[M_TOTAL * D_MODEL];
__device__ __align__(16) __nv_bfloat16 g_xl[M_TOTAL * D_MODEL];
__device__ __align__(16) __nv_bfloat16 g_Wth[4 * D_MODEL * D_MODEL]; // W^T hi [N,K]
__device__ __align__(16) __nv_bfloat16 g_Wtl[4 * D_MODEL * D_MODEL]; // W^T lo [N,K]
__device__ __align__(16) __nv_bfloat16 g_Oh[M_TOTAL * D_MODEL];
__device__ __align__(16) __nv_bfloat16 g_Ol[M_TOTAL * D_MODEL];

// ---------------------------------------------------------------------------
// helpers (compute_103-legal: ldmatrix / mma.sync / ex2.approx)
// ---------------------------------------------------------------------------
__device__ __forceinline__ uint32_t smem_u32(const void* p) {
    uint32_t a;
    asm("{ .reg .u64 t; cvta.to.shared.u64 t, %1; cvt.u32.u64 %0, t; }"
        : "=r"(a) : "l"(p));
    return a;
}
__device__ __forceinline__ void ldsm4(uint32_t* r, uint32_t addr) {
    asm volatile("ldmatrix.sync.aligned.m8n8.x4.shared.b16 {%0,%1,%2,%3}, [%4];"
        : "=r"(r[0]), "=r"(r[1]), "=r"(r[2]), "=r"(r[3]) : "r"(addr));
}
__device__ __forceinline__ void ldsm4t(uint32_t* r, uint32_t addr) {
    asm volatile("ldmatrix.sync.aligned.m8n8.x4.trans.shared.b16 {%0,%1,%2,%3}, [%4];"
        : "=r"(r[0]), "=r"(r[1]), "=r"(r[2]), "=r"(r[3]) : "r"(addr));
}
__device__ __forceinline__ void mma_bf16(float* c, const uint32_t* a,
                                         uint32_t b0, uint32_t b1) {
    asm volatile(
        "mma.sync.aligned.m16n8k16.row.col.f32.bf16.bf16.f32 "
        "{%0,%1,%2,%3}, {%4,%5,%6,%7}, {%8,%9}, {%0,%1,%2,%3};"
        : "+f"(c[0]), "+f"(c[1]), "+f"(c[2]), "+f"(c[3])
        : "r"(a[0]), "r"(a[1]), "r"(a[2]), "r"(a[3]), "r"(b0), "r"(b1));
}
__device__ __forceinline__ float exp2a(float x) {
    float r; asm("ex2.approx.f32 %0, %1;" : "=f"(r) : "f"(x)); return r;
}
// pack {lo, hi} floats -> bf16x2 (lo in bits[15:0])
__device__ __forceinline__ uint32_t bf16x2pk(float lo, float hi) {
    uint32_t r;
    asm("cvt.rn.bf16x2.f32 %0, %1, %2;" : "=r"(r) : "f"(hi), "f"(lo));
    return r;
}
__device__ __forceinline__ float bf_lo(uint32_t r) { return __uint_as_float(r << 16); }
__device__ __forceinline__ float bf_hi(uint32_t r) { return __uint_as_float(r & 0xffff0000u); }

// ---------------------------------------------------------------------------
// fp32 -> (bf16 hi, bf16 lo) split
// ---------------------------------------------------------------------------
__global__ __launch_bounds__(256) void convert_split(
    const float* __restrict__ X, __nv_bfloat16* __restrict__ H,
    __nv_bfloat16* __restrict__ L, int n4)
{
    int i = blockIdx.x * blockDim.x + threadIdx.x;
    if (i >= n4) return;
    float4 v = ((const float4*)X)[i];
    uint32_t h0 = bf16x2pk(v.x, v.y), h1 = bf16x2pk(v.z, v.w);
    uint32_t l0 = bf16x2pk(v.x - bf_lo(h0), v.y - bf_hi(h0));
    uint32_t l1 = bf16x2pk(v.z - bf_lo(h1), v.w - bf_hi(h1));
    ((uint2*)H)[i] = make_uint2(h0, h1);
    ((uint2*)L)[i] = make_uint2(l0, l1);
}

// ---------------------------------------------------------------------------
// W [K,N] fp32 -> W^T [N,K] bf16 hi/lo (32x32 smem transpose)
// ---------------------------------------------------------------------------
__global__ __launch_bounds__(256) void wtrans_split(
    const float* __restrict__ W, __nv_bfloat16* __restrict__ Th,
    __nv_bfloat16* __restrict__ Tl)
{
    __shared__ float t[32][33];
    const int bx = blockIdx.x * 32;   // n block
    const int by = blockIdx.y * 32;   // k block
    const int x = threadIdx.x, y = threadIdx.y;
    #pragma unroll
    for (int j = 0; j < 32; j += 8)
        t[y + j][x] = W[(by + y + j) * D_MODEL + bx + x];
    __syncthreads();
    #pragma unroll
    for (int j = 0; j < 32; j += 8) {
        float v = t[x][y + j];                 // (k=by+x, n=bx+y+j)
        __nv_bfloat16 h = __float2bfloat16_rn(v);
        __nv_bfloat16 l = __float2bfloat16_rn(v - __bfloat162float(h));
        Th[(bx + y + j) * D_MODEL + by + x] = h;
        Tl[(bx + y + j) * D_MODEL + by + x] = l;
    }
}

// ---------------------------------------------------------------------------
// bf16x3-split GEMM via mma.sync:  C = (A @ W + bias) * scale
// qkv_mode=1: write bf16 hi/lo scattered to [B,H,S,Hd] (Ch/Cl)
// qkv_mode=0: write fp32 row-major (Cf)
// ---------------------------------------------------------------------------
#define GK     32
#define NKCH   (D_MODEL / GK)        // 32
#define ROW_B  80
#define TILE_B (128 * ROW_B)
#define STG_B  (4 * TILE_B)
#define GEMM_SMEM (2 * STG_B)        // 81920

__global__ __launch_bounds__(256, 1)
void gemm_mma(const __nv_bfloat16* __restrict__ Ah,
              const __nv_bfloat16* __restrict__ Al,
              const __nv_bfloat16* __restrict__ Bh,
              const __nv_bfloat16* __restrict__ Bl,
              const float* __restrict__ bias,
              float* __restrict__ Cf,
              __nv_bfloat16* __restrict__ Ch,
              __nv_bfloat16* __restrict__ Cl,
              float scale, int qkv_mode)
{
    extern __shared__ char smem[];
    const uint32_t sb = smem_u32(smem);
    const int tid  = threadIdx.x;
    const int lane = tid & 31;
    const int wid  = tid >> 5;
    const int m0 = blockIdx.y * 128;
    const int n0 = blockIdx.x * 128;
    const int wm = (wid & 1) * 64;
    const int wn = (wid >> 1) * 32;

    const int lrow = tid >> 1;
    const int lhalf = tid & 1;
    const __nv_bfloat16* pAh = Ah + (size_t)(m0 + lrow) * D_MODEL;
    const __nv_bfloat16* pAl = Al + (size_t)(m0 + lrow) * D_MODEL;
    const __nv_bfloat16* pBh = Bh + (size_t)(n0 + lrow) * D_MODEL;
    const __nv_bfloat16* pBl = Bl + (size_t)(n0 + lrow) * D_MODEL;
    const uint32_t w0 = (uint32_t)lrow * ROW_B + (uint32_t)(lhalf * 2) * 16u;
    const uint32_t w1 = w0 + 16u;

    const uint32_t a_off = (uint32_t)(wm + (lane & 15)) * ROW_B
                         + (uint32_t)(lane >> 4) * 16u;
    const uint32_t b_off = (uint32_t)(wn + ((lane >> 4) << 3) + (lane & 7)) * ROW_B
                         + (uint32_t)((lane >> 3) & 1) * 16u;

    float acc[4][4][4];
    #pragma unroll
    for (int i = 0; i < 4; ++i)
        #pragma unroll
        for (int j = 0; j < 4; ++j)
            #pragma unroll
            for (int r = 0; r < 4; ++r) acc[i][j][r] = 0.f;

    uint4 rA_h[2], rA_l[2], rB_h[2], rB_l[2];
    {
        const int e0 = lhalf * 16;
        rA_h[0] = *(const uint4*)(pAh + e0);     rA_h[1] = *(const uint4*)(pAh + e0 + 8);
        rA_l[0] = *(const uint4*)(pAl + e0);     rA_l[1] = *(const uint4*)(pAl + e0 + 8);
        rB_h[0] = *(const uint4*)(pBh + e0);     rB_h[1] = *(const uint4*)(pBh + e0 + 8);
        rB_l[0] = *(const uint4*)(pBl + e0);     rB_l[1] = *(const uint4*)(pBl + e0 + 8);
        char* s = smem;
        *(uint4*)(s + w0) = rA_h[0];             *(uint4*)(s + w1) = rA_h[1];
        *(uint4*)(s + TILE_B + w0) = rA_l[0];    *(uint4*)(s + TILE_B + w1) = rA_l[1];
        *(uint4*)(s + 2*TILE_B + w0) = rB_h[0];  *(uint4*)(s + 2*TILE_B + w1) = rB_h[1];
        *(uint4*)(s + 3*TILE_B + w0) = rB_l[0];  *(uint4*)(s + 3*TILE_B + w1) = rB_l[1];
    }

    for (int i = 0; i < NKCH; ++i) {
        if (i + 1 < NKCH) {
            const int e = (i + 1) * GK + lhalf * 16;
            rA_h[0] = *(const uint4*)(pAh + e);     rA_h[1] = *(const uint4*)(pAh + e + 8);
            rA_l[0] = *(const uint4*)(pAl + e);     rA_l[1] = *(const uint4*)(pAl + e + 8);
            rB_h[0] = *(const uint4*)(pBh + e);     rB_h[1] = *(const uint4*)(pBh + e + 8);
            rB_l[0] = *(const uint4*)(pBl + e);     rB_l[1] = *(const uint4*)(pBl + e + 8);
        }
        __syncthreads();

        const uint32_t stg = sb + (uint32_t)(i & 1) * STG_B;
        #pragma unroll
        for (int ks = 0; ks < 2; ++ks) {
            uint32_t ah[4][4], al[4][4], bh[2][4], bl[2][4];
            #pragma unroll
            for (int mt = 0; mt < 4; ++mt) {
                ldsm4(ah[mt], stg + a_off + mt * (16 * ROW_B) + ks * 32);
                ldsm4(al[mt], stg + TILE_B + a_off + mt * (16 * ROW_B) + ks * 32);
            }
            #pragma unroll
            for (int ng = 0; ng < 2; ++ng) {
                ldsm4(bh[ng], stg + 2 * TILE_B + b_off + ng * (16 * ROW_B) + ks * 32);
                ldsm4(bl[ng], stg + 3 * TILE_B + b_off + ng * (16 * ROW_B) + ks * 32);
            }
            #pragma unroll
            for (int mt = 0; mt < 4; ++mt)
                #pragma unroll
                for (int n8 = 0; n8 < 4; ++n8) {
                    const int ng = n8 >> 1, hf = (n8 & 1) * 2;
                    mma_bf16(acc[mt][n8], ah[mt], bh[ng][hf], bh[ng][hf + 1]);
                    mma_bf16(acc[mt][n8], al[mt], bh[ng][hf], bh[ng][hf + 1]);
                    mma_bf16(acc[mt][n8], ah[mt], bl[ng][hf], bl[ng][hf + 1]);
                }
        }

        if (i + 1 < NKCH) {
            __syncthreads();
            char* s = smem + ((i + 1) & 1) * STG_B;
            *(uint4*)(s + w0) = rA_h[0];             *(uint4*)(s + w1) = rA_h[1];
            *(uint4*)(s + TILE_B + w0) = rA_l[0];    *(uint4*)(s + TILE_B + w1) = rA_l[1];
            *(uint4*)(s + 2*TILE_B + w0) = rB_h[0];  *(uint4*)(s + 2*TILE_B + w1) = rB_h[1];
            *(uint4*)(s + 3*TILE_B + w0) = rB_l[0];  *(uint4*)(s + 3*TILE_B + w1) = rB_l[1];
        }
    }

    // epilogue
    const int mrow = lane >> 2;
    const int ncol = (lane & 3) * 2;
    #pragma unroll
    for (int mt = 0; mt < 4; ++mt) {
        #pragma unroll
        for (int n8 = 0; n8 < 4; ++n8) {
            const int n = n0 + wn + n8 * 8 + ncol;
            const float bx = bias[n], by = bias[n + 1];
            #pragma unroll
            for (int h2 = 0; h2 < 2; ++h2) {
                const int m = m0 + wm + mt * 16 + mrow + h2 * 8;
                const float vx = (acc[mt][n8][h2 * 2 + 0] + bx) * scale;
                const float vy = (acc[mt][n8][h2 * 2 + 1] + by) * scale;
                const int b = m >> 11, s = m & (SEQ - 1);
                if (qkv_mode) {
                    const int hh = n >> 6, hd = n & 63;
                    const size_t idx =
                        ((size_t)(b * N_HEADS + hh) * SEQ + s) * HEAD_DIM + hd;
                    uint32_t ph = bf16x2pk(vx, vy);
                    uint32_t pl = bf16x2pk(vx - bf_lo(ph), vy - bf_hi(ph));
                    *(uint32_t*)&Ch[idx] = ph;
                    *(uint32_t*)&Cl[idx] = pl;
                } else {
                    float2 v; v.x = vx; v.y = vy;
                    *(float2*)&Cf[(size_t)m * D_MODEL + n] = v;
                }
            }
        }
    }
}

// ---------------------------------------------------------------------------
// Tensor-core causal flash attention (FA2-style register softmax).
// Q pre-scaled by 0.125*log2e; scores in log2 domain -> ex2.approx.
// 3-term splits: S = QhKh+QlKh+QhKl ; O += PhVh+PlVh+PhVl.
// CTA: 64 q-rows, 4 warps x 16 rows; loop over 64-key tiles.
// ---------------------------------------------------------------------------
#define SROWB 144                       // 72 bf16, conflict-free ldmatrix
#define ATILE (64 * SROWB)              // 9216 bytes per tensor tile
#define ATT_SMEM (6 * ATILE)            // Qh,Ql,Kh,Kl,Vh,Vl = 55296

__global__ __launch_bounds__(128)
void flash_mma(const __nv_bfloat16* __restrict__ Qh_,
               const __nv_bfloat16* __restrict__ Ql_,
               const __nv_bfloat16* __restrict__ Kh_,
               const __nv_bfloat16* __restrict__ Kl_,
               const __nv_bfloat16* __restrict__ Vh_,
               const __nv_bfloat16* __restrict__ Vl_,
               __nv_bfloat16* __restrict__ Oh,
               __nv_bfloat16* __restrict__ Ol)
{
    extern __shared__ char smem[];
    const uint32_t sb = smem_u32(smem);
    const uint32_t sK = sb + 2 * ATILE;      // Kh
    const uint32_t sV = sb + 4 * ATILE;      // Vh

    const int tid = threadIdx.x, lane = tid & 31, w = tid >> 5;
    const int bh = blockIdx.y;
    const int qb = gridDim.x - 1 - blockIdx.x;   // long blocks first
    const int q0 = qb * 64;
    const size_t base = (size_t)bh * SEQ * HEAD_DIM;

    const int lrow = tid >> 1, lhalf = tid & 1;
    const uint32_t ldoff = (uint32_t)lrow * SROWB + (uint32_t)lhalf * 64u;

    // ---- load Q tile (hi/lo) ----
    {
        const size_t g = base + (size_t)(q0 + lrow) * 64 + lhalf * 32;
        #pragma unroll
        for (int j = 0; j < 4; ++j) {
            *(uint4*)(smem + ldoff + j * 16) = *(const uint4*)(Qh_ + g + j * 8);
            *(uint4*)(smem + ATILE + ldoff + j * 16) = *(const uint4*)(Ql_ + g + j * 8);
        }
    }
    __syncthreads();

    // ---- Q fragments ----
    uint32_t qh[4][4], qlf[4][4];
    {
        const int r = (w << 4) + (lane & 15);
        const int c = (lane >> 4) << 3;
        #pragma unroll
        for (int kc = 0; kc < 4; ++kc) {
            const uint32_t a = sb + (uint32_t)r * SROWB + (uint32_t)(kc * 16 + c) * 2;
            ldsm4(qh[kc], a);
            ldsm4(qlf[kc], a + ATILE);
        }
    }

    // ldmatrix address components
    const uint32_t k_nr = (uint32_t)((lane & 7) + ((lane >> 4) << 3));
    const uint32_t k_nc = (uint32_t)(((lane >> 3) & 1) << 3);
    const uint32_t v_nr = (uint32_t)((lane & 7) + (((lane >> 3) & 1) << 3));
    const uint32_t v_nc = (uint32_t)((lane >> 4) << 3);

    float o[8][4];
    #pragma unroll
    for (int i = 0; i < 8; ++i)
        #pragma unroll
        for (int j = 0; j < 4; ++j) o[i][j] = 0.f;
    float m0 = -1e30f, m1 = -1e30f, l0 = 0.f, l1 = 0.f;

    for (int kt = 0; kt <= q0; kt += 64) {
        if (kt) __syncthreads();
        // ---- load K/V tiles (hi/lo) ----
        {
            const size_t g = base + (size_t)(kt + lrow) * 64 + lhalf * 32;
            #pragma unroll
            for (int j = 0; j < 4; ++j) {
                *(uint4*)(smem + 2*ATILE + ldoff + j*16) = *(const uint4*)(Kh_ + g + j*8);
                *(uint4*)(smem + 3*ATILE + ldoff + j*16) = *(const uint4*)(Kl_ + g + j*8);
                *(uint4*)(smem + 4*ATILE + ldoff + j*16) = *(const uint4*)(Vh_ + g + j*8);
                *(uint4*)(smem + 5*ATILE + ldoff + j*16) = *(const uint4*)(Vl_ + g + j*8);
            }
        }
        __syncthreads();

        // ---- S = Q K^T (3-term split) ----
        float s[8][4];
        #pragma unroll
        for (int i = 0; i < 8; ++i)
            #pragma unroll
            for (int j = 0; j < 4; ++j) s[i][j] = 0.f;

        #pragma unroll
        for (int nbp = 0; nbp < 4; ++nbp) {
            #pragma unroll
            for (int kc = 0; kc < 4; ++kc) {
                uint32_t kh[4], kl[4];
                const uint32_t a = sK + (uint32_t)(nbp * 16 + k_nr) * SROWB
                                 + (uint32_t)(kc * 16 + k_nc) * 2;
                ldsm4(kh, a);
                ldsm4(kl, a + ATILE);
                mma_bf16(s[2*nbp],   qh[kc],  kh[0], kh[1]);
                mma_bf16(s[2*nbp],   qlf[kc], kh[0], kh[1]);
                mma_bf16(s[2*nbp],   qh[kc],  kl[0], kl[1]);
                mma_bf16(s[2*nbp+1], qh[kc],  kh[2], kh[3]);
                mma_bf16(s[2*nbp+1], qlf[kc], kh[2], kh[3]);
                mma_bf16(s[2*nbp+1], qh[kc],  kl[2], kl[3]);
            }
        }

        // ---- causal mask (diagonal tile only) ----
        if (kt == q0) {
            const int rb = (w << 4) + (lane >> 2);
            #pragma unroll
            for (int nb = 0; nb < 8; ++nb) {
                const int c = nb * 8 + ((lane & 3) << 1);
                if (c     > rb)     s[nb][0] = -1e30f;
                if (c + 1 > rb)     s[nb][1] = -1e30f;
                if (c     > rb + 8) s[nb][2] = -1e30f;
                if (c + 1 > rb + 8) s[nb][3] = -1e30f;
            }
        }

        // ---- online softmax (log2 domain) ----
        float mt0 = -1e30f, mt1 = -1e30f;
        #pragma unroll
        for (int nb = 0; nb < 8; ++nb) {
            mt0 = fmaxf(mt0, fmaxf(s[nb][0], s[nb][1]));
            mt1 = fmaxf(mt1, fmaxf(s[nb][2], s[nb][3]));
        }
        mt0 = fmaxf(mt0, __shfl_xor_sync(0xffffffffu, mt0, 1));
        mt0 = fmaxf(mt0, __shfl_xor_sync(0xffffffffu, mt0, 2));
        mt1 = fmaxf(mt1, __shfl_xor_sync(0xffffffffu, mt1, 1));
        mt1 = fmaxf(mt1, __shfl_xor_sync(0xffffffffu, mt1, 2));
        const float mn0 = fmaxf(m0, mt0), mn1 = fmaxf(m1, mt1);
        const float c0 = exp2a(m0 - mn0), c1 = exp2a(m1 - mn1);
        m0 = mn0; m1 = mn1;
        l0 *= c0;  l1 *= c1;

        uint32_t ph[4][4], pl[4][4];
        #pragma unroll
        for (int nb = 0; nb < 8; ++nb) {
            const float p0 = exp2a(s[nb][0] - mn0);
            const float p1 = exp2a(s[nb][1] - mn0);
            const float p2 = exp2a(s[nb][2] - mn1);
            const float p3 = exp2a(s[nb][3] - mn1);
            l0 += p0 + p1;  l1 += p2 + p3;
            o[nb][0] *= c0; o[nb][1] *= c0; o[nb][2] *= c1; o[nb][3] *= c1;
            const int j = nb >> 1, q = (nb & 1) << 1;
            const uint32_t hA = bf16x2pk(p0, p1);
            const uint32_t hB = bf16x2pk(p2, p3);
            ph[j][q]     = hA;
            ph[j][q + 1] = hB;
            pl[j][q]     = bf16x2pk(p0 - bf_lo(hA), p1 - bf_hi(hA));
            pl[j][q + 1] = bf16x2pk(p2 - bf_lo(hB), p3 - bf_hi(hB));
        }

        // ---- O += P V (3-term split), V^T via ldmatrix.trans ----
        #pragma unroll
        for (int j = 0; j < 4; ++j) {
            #pragma unroll
            for (int nbp = 0; nbp < 4; ++nbp) {
                uint32_t vh[4], vl[4];
                const uint32_t a = sV + (uint32_t)(j * 16 + v_nr) * SROWB
                                 + (uint32_t)(nbp * 16 + v_nc) * 2;
                ldsm4t(vh, a);
                ldsm4t(vl, a + ATILE);
                mma_bf16(o[2*nbp],   ph[j], vh[0], vh[1]);
                mma_bf16(o[2*nbp],   pl[j], vh[0], vh[1]);
                mma_bf16(o[2*nbp],   ph[j], vl[0], vl[1]);
                mma_bf16(o[2*nbp+1], ph[j], vh[2], vh[3]);
                mma_bf16(o[2*nbp+1], pl[j], vh[2], vh[3]);
                mma_bf16(o[2*nbp+1], ph[j], vl[2], vl[3]);
            }
        }
    }

    // ---- finalize: row sums, normalize, write O (bf16 hi/lo, [B,S,D]) ----
    l0 += __shfl_xor_sync(0xffffffffu, l0, 1);
    l0 += __shfl_xor_sync(0xffffffffu, l0, 2);
    l1 += __shfl_xor_sync(0xffffffffu, l1, 1);
    l1 += __shfl_xor_sync(0xffffffffu, l1, 2);
    const float inv0 = 1.f / l0, inv1 = 1.f / l1;

    const int b = bh >> 4, h = bh & 15;
    const int r0g = q0 + (w << 4) + (lane >> 2);
    #pragma unroll
    for (int nb = 0; nb < 8; ++nb) {
        const int col = h * 64 + nb * 8 + ((lane & 3) << 1);
        {
            const float x0 = o[nb][0] * inv0, x1 = o[nb][1] * inv0;
            const uint32_t hh = bf16x2pk(x0, x1);
            const uint32_t ll = bf16x2pk(x0 - bf_lo(hh), x1 - bf_hi(hh));
            const size_t idx = (size_t)(b * SEQ + r0g) * D_MODEL + col;
            *(uint32_t*)&Oh[idx] = hh;
            *(uint32_t*)&Ol[idx] = ll;
        }
        {
            const float x2 = o[nb][2] * inv1, x3 = o[nb][3] * inv1;
            const uint32_t hh = bf16x2pk(x2, x3);
            const uint32_t ll = bf16x2pk(x2 - bf_lo(hh), x3 - bf_hi(hh));
            const size_t idx = (size_t)(b * SEQ + r0g + 8) * D_MODEL + col;
            *(uint32_t*)&Oh[idx] = hh;
            *(uint32_t*)&Ol[idx] = ll;
        }
    }
}

// ---------------------------------------------------------------------------
extern "C" void kernel_launch(void* const* d_in, const int* in_sizes, int n_in,
                              void* d_out, int out_size)
{
    (void)in_sizes; (void)n_in; (void)out_size;
    const float* x  = (const float*)d_in[0];
    const float* Wq = (const float*)d_in[1];
    const float* bq = (const float*)d_in[2];
    const float* Wk = (const float*)d_in[3];
    const float* bk = (const float*)d_in[4];
    const float* Wv = (const float*)d_in[5];
    const float* bv = (const float*)d_in[6];
    const float* Wo = (const float*)d_in[7];
    const float* bo = (const float*)d_in[8];
    float* out = (float*)d_out;

    __nv_bfloat16 *Qh, *Ql, *Kh, *Kl, *Vh, *Vl, *xh, *xl, *Wth, *Wtl, *Oh, *Ol;
    cudaGetSymbolAddress((void**)&Qh,  g_Qh);  cudaGetSymbolAddress((void**)&Ql, g_Ql);
    cudaGetSymbolAddress((void**)&Kh,  g_Kh);  cudaGetSymbolAddress((void**)&Kl, g_Kl);
    cudaGetSymbolAddress((void**)&Vh,  g_Vh);  cudaGetSymbolAddress((void**)&Vl, g_Vl);
    cudaGetSymbolAddress((void**)&xh,  g_xh);  cudaGetSymbolAddress((void**)&xl, g_xl);
    cudaGetSymbolAddress((void**)&Wth, g_Wth); cudaGetSymbolAddress((void**)&Wtl, g_Wtl);
    cudaGetSymbolAddress((void**)&Oh,  g_Oh);  cudaGetSymbolAddress((void**)&Ol, g_Ol);

    cudaFuncSetAttribute(gemm_mma,
                         cudaFuncAttributeMaxDynamicSharedMemorySize, GEMM_SMEM);
    cudaFuncSetAttribute(flash_mma,
                         cudaFuncAttributeMaxDynamicSharedMemorySize, ATT_SMEM);

    const size_t WSZ = (size_t)D_MODEL * D_MODEL;

    convert_split<<<(M_TOTAL * D_MODEL / 4 + 255) / 256, 256>>>(
        x, xh, xl, M_TOTAL * D_MODEL / 4);

    dim3 wtg(32, 32), wtb(32, 8);
    wtrans_split<<<wtg, wtb>>>(Wq, Wth + 0 * WSZ, Wtl + 0 * WSZ);
    wtrans_split<<<wtg, wtb>>>(Wk, Wth + 1 * WSZ, Wtl + 1 * WSZ);
    wtrans_split<<<wtg, wtb>>>(Wv, Wth + 2 * WSZ, Wtl + 2 * WSZ);
    wtrans_split<<<wtg, wtb>>>(Wo, Wth + 3 * WSZ, Wtl + 3 * WSZ);

    dim3 gg(D_MODEL / 128, M_TOTAL / 128);
    // Q scaled by 0.125*log2e (scores land in log2 domain for ex2)
    gemm_mma<<<gg, 256, GEMM_SMEM>>>(xh, xl, Wth + 0 * WSZ, Wtl + 0 * WSZ,
                                     bq, nullptr, Qh, Ql, QSCALE, 1);
    gemm_mma<<<gg, 256, GEMM_SMEM>>>(xh, xl, Wth + 1 * WSZ, Wtl + 1 * WSZ,
                                     bk, nullptr, Kh, Kl, 1.0f, 1);
    gemm_mma<<<gg, 256, GEMM_SMEM>>>(xh, xl, Wth + 2 * WSZ, Wtl + 2 * WSZ,
                                     bv, nullptr, Vh, Vl, 1.0f, 1);

    dim3 ga(SEQ / 64, BATCH * N_HEADS);
    flash_mma<<<ga, 128, ATT_SMEM>>>(Qh, Ql, Kh, Kl, Vh, Vl, Oh, Ol);

    gemm_mma<<<gg, 256, GEMM_SMEM>>>(Oh, Ol, Wth + 3 * WSZ, Wtl + 3 * WSZ,
                                     bo, out, nullptr, nullptr, 1.0f, 0);
}

// round 5
// speedup vs baseline: 3.7786x; 1.1311x over previous
#include <cuda_runtime.h>
#include <cuda_bf16.h>
#include <cuda_fp16.h>
#include <cstdint>

#define D_MODEL  1024
#define N_HEADS  16
#define HEAD_DIM 64
#define BATCH    2
#define SEQ      2048
#define M_TOTAL  (BATCH * SEQ)   // 4096
#define QSCALE   0.18033688011112042f   // 0.125 * log2(e)

// ---------------------------------------------------------------------------
// Device-global scratch (allocation-free rule)
// ---------------------------------------------------------------------------
#define PHSZ (BATCH * N_HEADS * SEQ * HEAD_DIM)   // 4M elems
__device__ __align__(16) __half g_Qh[PHSZ], g_Ql[PHSZ];
__device__ __align__(16) __half g_Kh[PHSZ], g_Kl[PHSZ];
__device__ __align__(16) __half g_Vh[PHSZ];
__device__ __align__(16) __nv_bfloat16 g_xh[M_TOTAL * D_MODEL];
__device__ __align__(16) __nv_bfloat16 g_xl[M_TOTAL * D_MODEL];
__device__ __align__(16) __nv_bfloat16 g_Wth[4 * D_MODEL * D_MODEL]; // W^T hi [N,K]
__device__ __align__(16) __nv_bfloat16 g_Wtl[4 * D_MODEL * D_MODEL]; // W^T lo [N,K]
__device__ __align__(16) __nv_bfloat16 g_Oh[M_TOTAL * D_MODEL];
__device__ __align__(16) __nv_bfloat16 g_Ol[M_TOTAL * D_MODEL];

// ---------------------------------------------------------------------------
// helpers (compute_103-legal: ldmatrix / mma.sync / cp.async / ex2.approx)
// ---------------------------------------------------------------------------
__device__ __forceinline__ uint32_t smem_u32(const void* p) {
    uint32_t a;
    asm("{ .reg .u64 t; cvta.to.shared.u64 t, %1; cvt.u32.u64 %0, t; }"
        : "=r"(a) : "l"(p));
    return a;
}
__device__ __forceinline__ void ldsm4(uint32_t* r, uint32_t addr) {
    asm volatile("ldmatrix.sync.aligned.m8n8.x4.shared.b16 {%0,%1,%2,%3}, [%4];"
        : "=r"(r[0]), "=r"(r[1]), "=r"(r[2]), "=r"(r[3]) : "r"(addr));
}
__device__ __forceinline__ void ldsm4t(uint32_t* r, uint32_t addr) {
    asm volatile("ldmatrix.sync.aligned.m8n8.x4.trans.shared.b16 {%0,%1,%2,%3}, [%4];"
        : "=r"(r[0]), "=r"(r[1]), "=r"(r[2]), "=r"(r[3]) : "r"(addr));
}
__device__ __forceinline__ void mma_bf16(float* c, const uint32_t* a,
                                         uint32_t b0, uint32_t b1) {
    asm volatile(
        "mma.sync.aligned.m16n8k16.row.col.f32.bf16.bf16.f32 "
        "{%0,%1,%2,%3}, {%4,%5,%6,%7}, {%8,%9}, {%0,%1,%2,%3};"
        : "+f"(c[0]), "+f"(c[1]), "+f"(c[2]), "+f"(c[3])
        : "r"(a[0]), "r"(a[1]), "r"(a[2]), "r"(a[3]), "r"(b0), "r"(b1));
}
__device__ __forceinline__ void mma_f16(float* c, const uint32_t* a,
                                        uint32_t b0, uint32_t b1) {
    asm volatile(
        "mma.sync.aligned.m16n8k16.row.col.f32.f16.f16.f32 "
        "{%0,%1,%2,%3}, {%4,%5,%6,%7}, {%8,%9}, {%0,%1,%2,%3};"
        : "+f"(c[0]), "+f"(c[1]), "+f"(c[2]), "+f"(c[3])
        : "r"(a[0]), "r"(a[1]), "r"(a[2]), "r"(a[3]), "r"(b0), "r"(b1));
}
__device__ __forceinline__ float exp2a(float x) {
    float r; asm("ex2.approx.f32 %0, %1;" : "=f"(r) : "f"(x)); return r;
}
__device__ __forceinline__ uint32_t bf16x2pk(float lo, float hi) {
    uint32_t r;
    asm("cvt.rn.bf16x2.f32 %0, %1, %2;" : "=r"(r) : "f"(hi), "f"(lo));
    return r;
}
__device__ __forceinline__ uint32_t f16x2pk(float lo, float hi) {
    uint32_t r;
    asm("cvt.rn.f16x2.f32 %0, %1, %2;" : "=r"(r) : "f"(hi), "f"(lo));
    return r;
}
__device__ __forceinline__ float bf_lo(uint32_t r) { return __uint_as_float(r << 16); }
__device__ __forceinline__ float bf_hi(uint32_t r) { return __uint_as_float(r & 0xffff0000u); }

#define CP16(saddr, gptr) \
    asm volatile("cp.async.cg.shared.global [%0], [%1], 16;" \
        :: "r"(saddr), "l"(gptr) : "memory")
#define CP_COMMIT() asm volatile("cp.async.commit_group;" ::: "memory")
#define CP_WAIT0()  asm volatile("cp.async.wait_group 0;" ::: "memory")
#define CP_WAIT1()  asm volatile("cp.async.wait_group 1;" ::: "memory")

// ---------------------------------------------------------------------------
// fp32 -> (bf16 hi, bf16 lo) split
// ---------------------------------------------------------------------------
__global__ __launch_bounds__(256) void convert_split(
    const float* __restrict__ X, __nv_bfloat16* __restrict__ H,
    __nv_bfloat16* __restrict__ L, int n4)
{
    int i = blockIdx.x * blockDim.x + threadIdx.x;
    if (i >= n4) return;
    float4 v = ((const float4*)X)[i];
    uint32_t h0 = bf16x2pk(v.x, v.y), h1 = bf16x2pk(v.z, v.w);
    uint32_t l0 = bf16x2pk(v.x - bf_lo(h0), v.y - bf_hi(h0));
    uint32_t l1 = bf16x2pk(v.z - bf_lo(h1), v.w - bf_hi(h1));
    ((uint2*)H)[i] = make_uint2(h0, h1);
    ((uint2*)L)[i] = make_uint2(l0, l1);
}

// ---------------------------------------------------------------------------
// W [K,N] fp32 -> W^T [N,K] bf16 hi/lo (32x32 smem transpose)
// ---------------------------------------------------------------------------
__global__ __launch_bounds__(256) void wtrans_split(
    const float* __restrict__ W, __nv_bfloat16* __restrict__ Th,
    __nv_bfloat16* __restrict__ Tl)
{
    __shared__ float t[32][33];
    const int bx = blockIdx.x * 32;
    const int by = blockIdx.y * 32;
    const int x = threadIdx.x, y = threadIdx.y;
    #pragma unroll
    for (int j = 0; j < 32; j += 8)
        t[y + j][x] = W[(by + y + j) * D_MODEL + bx + x];
    __syncthreads();
    #pragma unroll
    for (int j = 0; j < 32; j += 8) {
        float v = t[x][y + j];
        __nv_bfloat16 h = __float2bfloat16_rn(v);
        __nv_bfloat16 l = __float2bfloat16_rn(v - __bfloat162float(h));
        Th[(bx + y + j) * D_MODEL + by + x] = h;
        Tl[(bx + y + j) * D_MODEL + by + x] = l;
    }
}

// ---------------------------------------------------------------------------
// Shared GEMM mainloop macro-free body: bf16x3 via mma.sync, 128x128 tile.
// Two instantiations: QKV (fp16 hi/lo scatter out, grid.z selects q/k/v)
// and OUT (fp32 row-major out).
// ---------------------------------------------------------------------------
#define GK     32
#define NKCH   (D_MODEL / GK)        // 32
#define ROW_B  80
#define TILE_B (128 * ROW_B)
#define STG_B  (4 * TILE_B)
#define GEMM_SMEM (2 * STG_B)        // 81920

// computes acc[4][4][4] for this thread; declared as a device function
__device__ __forceinline__ void gemm_core(
    const __nv_bfloat16* __restrict__ Ah, const __nv_bfloat16* __restrict__ Al,
    const __nv_bfloat16* __restrict__ Bh, const __nv_bfloat16* __restrict__ Bl,
    char* smem, uint32_t sb, int m0, int n0, float acc[4][4][4])
{
    const int tid  = threadIdx.x;
    const int lane = tid & 31;
    const int wid  = tid >> 5;
    const int wm = (wid & 1) * 64;
    const int wn = (wid >> 1) * 32;

    const int lrow = tid >> 1;
    const int lhalf = tid & 1;
    const __nv_bfloat16* pAh = Ah + (size_t)(m0 + lrow) * D_MODEL;
    const __nv_bfloat16* pAl = Al + (size_t)(m0 + lrow) * D_MODEL;
    const __nv_bfloat16* pBh = Bh + (size_t)(n0 + lrow) * D_MODEL;
    const __nv_bfloat16* pBl = Bl + (size_t)(n0 + lrow) * D_MODEL;
    const uint32_t w0 = (uint32_t)lrow * ROW_B + (uint32_t)(lhalf * 2) * 16u;
    const uint32_t w1 = w0 + 16u;

    const uint32_t a_off = (uint32_t)(wm + (lane & 15)) * ROW_B
                         + (uint32_t)(lane >> 4) * 16u;
    const uint32_t b_off = (uint32_t)(wn + ((lane >> 4) << 3) + (lane & 7)) * ROW_B
                         + (uint32_t)((lane >> 3) & 1) * 16u;

    #pragma unroll
    for (int i = 0; i < 4; ++i)
        #pragma unroll
        for (int j = 0; j < 4; ++j)
            #pragma unroll
            for (int r = 0; r < 4; ++r) acc[i][j][r] = 0.f;

    uint4 rA_h[2], rA_l[2], rB_h[2], rB_l[2];
    {
        const int e0 = lhalf * 16;
        rA_h[0] = *(const uint4*)(pAh + e0);     rA_h[1] = *(const uint4*)(pAh + e0 + 8);
        rA_l[0] = *(const uint4*)(pAl + e0);     rA_l[1] = *(const uint4*)(pAl + e0 + 8);
        rB_h[0] = *(const uint4*)(pBh + e0);     rB_h[1] = *(const uint4*)(pBh + e0 + 8);
        rB_l[0] = *(const uint4*)(pBl + e0);     rB_l[1] = *(const uint4*)(pBl + e0 + 8);
        char* s = smem;
        *(uint4*)(s + w0) = rA_h[0];             *(uint4*)(s + w1) = rA_h[1];
        *(uint4*)(s + TILE_B + w0) = rA_l[0];    *(uint4*)(s + TILE_B + w1) = rA_l[1];
        *(uint4*)(s + 2*TILE_B + w0) = rB_h[0];  *(uint4*)(s + 2*TILE_B + w1) = rB_h[1];
        *(uint4*)(s + 3*TILE_B + w0) = rB_l[0];  *(uint4*)(s + 3*TILE_B + w1) = rB_l[1];
    }

    for (int i = 0; i < NKCH; ++i) {
        if (i + 1 < NKCH) {
            const int e = (i + 1) * GK + lhalf * 16;
            rA_h[0] = *(const uint4*)(pAh + e);     rA_h[1] = *(const uint4*)(pAh + e + 8);
            rA_l[0] = *(const uint4*)(pAl + e);     rA_l[1] = *(const uint4*)(pAl + e + 8);
            rB_h[0] = *(const uint4*)(pBh + e);     rB_h[1] = *(const uint4*)(pBh + e + 8);
            rB_l[0] = *(const uint4*)(pBl + e);     rB_l[1] = *(const uint4*)(pBl + e + 8);
        }
        __syncthreads();

        const uint32_t stg = sb + (uint32_t)(i & 1) * STG_B;
        #pragma unroll
        for (int ks = 0; ks < 2; ++ks) {
            uint32_t ah[4][4], al[4][4], bh[2][4], bl[2][4];
            #pragma unroll
            for (int mt = 0; mt < 4; ++mt) {
                ldsm4(ah[mt], stg + a_off + mt * (16 * ROW_B) + ks * 32);
                ldsm4(al[mt], stg + TILE_B + a_off + mt * (16 * ROW_B) + ks * 32);
            }
            #pragma unroll
            for (int ng = 0; ng < 2; ++ng) {
                ldsm4(bh[ng], stg + 2 * TILE_B + b_off + ng * (16 * ROW_B) + ks * 32);
                ldsm4(bl[ng], stg + 3 * TILE_B + b_off + ng * (16 * ROW_B) + ks * 32);
            }
            #pragma unroll
            for (int mt = 0; mt < 4; ++mt)
                #pragma unroll
                for (int n8 = 0; n8 < 4; ++n8) {
                    const int ng = n8 >> 1, hf = (n8 & 1) * 2;
                    mma_bf16(acc[mt][n8], ah[mt], bh[ng][hf], bh[ng][hf + 1]);
                    mma_bf16(acc[mt][n8], al[mt], bh[ng][hf], bh[ng][hf + 1]);
                    mma_bf16(acc[mt][n8], ah[mt], bl[ng][hf], bl[ng][hf + 1]);
                }
        }

        if (i + 1 < NKCH) {
            __syncthreads();
            char* s = smem + ((i + 1) & 1) * STG_B;
            *(uint4*)(s + w0) = rA_h[0];             *(uint4*)(s + w1) = rA_h[1];
            *(uint4*)(s + TILE_B + w0) = rA_l[0];    *(uint4*)(s + TILE_B + w1) = rA_l[1];
            *(uint4*)(s + 2*TILE_B + w0) = rB_h[0];  *(uint4*)(s + 2*TILE_B + w1) = rB_h[1];
            *(uint4*)(s + 3*TILE_B + w0) = rB_l[0];  *(uint4*)(s + 3*TILE_B + w1) = rB_l[1];
        }
    }
}

// QKV projections fused: grid (8, 32, 3); z: 0=Q, 1=K, 2=V.
// Output fp16 hi/lo (V: hi only) scattered to [B,H,S,Hd].
__global__ __launch_bounds__(256, 1)
void gemm_qkv(const __nv_bfloat16* __restrict__ xh,
              const __nv_bfloat16* __restrict__ xl,
              const __nv_bfloat16* __restrict__ Wth,
              const __nv_bfloat16* __restrict__ Wtl,
              const float* __restrict__ bq, const float* __restrict__ bk,
              const float* __restrict__ bv,
              __half* __restrict__ Qh, __half* __restrict__ Ql,
              __half* __restrict__ Kh, __half* __restrict__ Kl,
              __half* __restrict__ Vh)
{
    extern __shared__ char smem[];
    const uint32_t sb = smem_u32(smem);
    const int z = blockIdx.z;
    const size_t WSZ = (size_t)D_MODEL * D_MODEL;
    const __nv_bfloat16* Bh = Wth + (size_t)z * WSZ;
    const __nv_bfloat16* Bl = Wtl + (size_t)z * WSZ;
    const float* bias = (z == 0) ? bq : (z == 1) ? bk : bv;
    const float scale = (z == 0) ? QSCALE : 1.0f;
    __half* Ch = (z == 0) ? Qh : (z == 1) ? Kh : Vh;
    __half* Cl = (z == 0) ? Ql : Kl;   // unused for z==2

    const int m0 = blockIdx.y * 128;
    const int n0 = blockIdx.x * 128;

    float acc[4][4][4];
    gemm_core(xh, xl, Bh, Bl, smem, sb, m0, n0, acc);

    const int lane = threadIdx.x & 31;
    const int wid  = threadIdx.x >> 5;
    const int wm = (wid & 1) * 64, wn = (wid >> 1) * 32;
    const int mrow = lane >> 2, ncol = (lane & 3) * 2;
    #pragma unroll
    for (int mt = 0; mt < 4; ++mt) {
        #pragma unroll
        for (int n8 = 0; n8 < 4; ++n8) {
            const int n = n0 + wn + n8 * 8 + ncol;
            const float bx = bias[n], by = bias[n + 1];
            #pragma unroll
            for (int h2 = 0; h2 < 2; ++h2) {
                const int m = m0 + wm + mt * 16 + mrow + h2 * 8;
                const float vx = (acc[mt][n8][h2 * 2 + 0] + bx) * scale;
                const float vy = (acc[mt][n8][h2 * 2 + 1] + by) * scale;
                const int b = m >> 11, s = m & (SEQ - 1);
                const int hh = n >> 6, hd = n & 63;
                const size_t idx =
                    ((size_t)(b * N_HEADS + hh) * SEQ + s) * HEAD_DIM + hd;
                const uint32_t ph = f16x2pk(vx, vy);
                *(uint32_t*)&Ch[idx] = ph;
                if (z != 2) {
                    const __half2 hp = *(const __half2*)&ph;
                    const uint32_t pl = f16x2pk(vx - __half2float(hp.x),
                                                vy - __half2float(hp.y));
                    *(uint32_t*)&Cl[idx] = pl;
                }
            }
        }
    }
}

// Output projection: fp32 out row-major.
__global__ __launch_bounds__(256, 1)
void gemm_out(const __nv_bfloat16* __restrict__ Ah,
              const __nv_bfloat16* __restrict__ Al,
              const __nv_bfloat16* __restrict__ Bh,
              const __nv_bfloat16* __restrict__ Bl,
              const float* __restrict__ bias, float* __restrict__ C)
{
    extern __shared__ char smem[];
    const uint32_t sb = smem_u32(smem);
    const int m0 = blockIdx.y * 128;
    const int n0 = blockIdx.x * 128;

    float acc[4][4][4];
    gemm_core(Ah, Al, Bh, Bl, smem, sb, m0, n0, acc);

    const int lane = threadIdx.x & 31;
    const int wid  = threadIdx.x >> 5;
    const int wm = (wid & 1) * 64, wn = (wid >> 1) * 32;
    const int mrow = lane >> 2, ncol = (lane & 3) * 2;
    #pragma unroll
    for (int mt = 0; mt < 4; ++mt) {
        #pragma unroll
        for (int n8 = 0; n8 < 4; ++n8) {
            const int n = n0 + wn + n8 * 8 + ncol;
            const float bx = bias[n], by = bias[n + 1];
            #pragma unroll
            for (int h2 = 0; h2 < 2; ++h2) {
                const int m = m0 + wm + mt * 16 + mrow + h2 * 8;
                float2 v;
                v.x = acc[mt][n8][h2 * 2 + 0] + bx;
                v.y = acc[mt][n8][h2 * 2 + 1] + by;
                *(float2*)&C[(size_t)m * D_MODEL + n] = v;
            }
        }
    }
}

// ---------------------------------------------------------------------------
// Tensor-core causal flash attention, fp16 operands.
// S = QhKh + QlKh + QhKl (3-term, ~exact).  O += Ph·Vh (1-term, err ~2^-11.5).
// cp.async double-buffered K/V pipeline; skip-rescale on unchanged max.
// CTA: 64 q-rows, 4 warps; smem = Qh,Ql + 2 stages x (Kh,Kl,Vh).
// ---------------------------------------------------------------------------
#define SROWB 144
#define ATILE (64 * SROWB)               // 9216
#define ATT_SMEM (8 * ATILE)             // 73728

__device__ __forceinline__ void cp_tile3(uint32_t sbase, const __half* gK,
                                         const __half* gKl, const __half* gV,
                                         int tid)
{
    #pragma unroll
    for (int i = 0; i < 4; ++i) {
        const int c = tid + 128 * i;
        const uint32_t sa = (uint32_t)(c >> 3) * SROWB + (uint32_t)(c & 7) * 16u;
        CP16(sbase + sa, gK + 8 * c);
        CP16(sbase + ATILE + sa, gKl + 8 * c);
        CP16(sbase + 2 * ATILE + sa, gV + 8 * c);
    }
}

__global__ __launch_bounds__(128)
void flash_mma(const __half* __restrict__ Qh_, const __half* __restrict__ Ql_,
               const __half* __restrict__ Kh_, const __half* __restrict__ Kl_,
               const __half* __restrict__ Vh_,
               __nv_bfloat16* __restrict__ Oh, __nv_bfloat16* __restrict__ Ol)
{
    extern __shared__ char smem[];
    const uint32_t sb = smem_u32(smem);

    const int tid = threadIdx.x, lane = tid & 31, w = tid >> 5;
    const int bh = blockIdx.y;
    const int qb = gridDim.x - 1 - blockIdx.x;   // long blocks first
    const int q0 = qb * 64;
    const size_t base = (size_t)bh * SEQ * HEAD_DIM;

    // prologue: Q (2 subtiles) + K/V stage 0, one cp.async group
    {
        const __half* gQh = Qh_ + base + (size_t)q0 * 64;
        const __half* gQl = Ql_ + base + (size_t)q0 * 64;
        #pragma unroll
        for (int i = 0; i < 4; ++i) {
            const int c = tid + 128 * i;
            const uint32_t sa = (uint32_t)(c >> 3) * SROWB + (uint32_t)(c & 7) * 16u;
            CP16(sb + sa, gQh + 8 * c);
            CP16(sb + ATILE + sa, gQl + 8 * c);
        }
        cp_tile3(sb + 2 * ATILE, Kh_ + base, Kl_ + base, Vh_ + base, tid);
        CP_COMMIT();
    }

    // ldmatrix address components
    const uint32_t k_nr = (uint32_t)((lane & 7) + ((lane >> 4) << 3));
    const uint32_t k_nc = (uint32_t)(((lane >> 3) & 1) << 3);
    const uint32_t v_nr = (uint32_t)((lane & 7) + (((lane >> 3) & 1) << 3));
    const uint32_t v_nc = (uint32_t)((lane >> 4) << 3);

    uint32_t qh[4][4], qlf[4][4];
    float o[8][4];
    #pragma unroll
    for (int i = 0; i < 8; ++i)
        #pragma unroll
        for (int j = 0; j < 4; ++j) o[i][j] = 0.f;
    float m0 = -1e30f, m1 = -1e30f, l0 = 0.f, l1 = 0.f;

    const int nt = q0 >> 6;           // last tile index
    for (int it = 0; it <= nt; ++it) {
        __syncthreads();              // all warps done reading stage it^1
        if (it < nt) {
            const size_t g = base + (size_t)(it + 1) * 64 * 64;
            cp_tile3(sb + 2 * ATILE + (uint32_t)((it + 1) & 1) * 3 * ATILE,
                     Kh_ + g, Kl_ + g, Vh_ + g, tid);
            CP_COMMIT();
            CP_WAIT1();               // stage it complete, it+1 in flight
        } else {
            CP_WAIT0();
        }
        __syncthreads();

        if (it == 0) {                // Q fragments (once)
            const int r = (w << 4) + (lane & 15);
            const int c = (lane >> 4) << 3;
            #pragma unroll
            for (int kc = 0; kc < 4; ++kc) {
                const uint32_t a = sb + (uint32_t)r * SROWB
                                 + (uint32_t)(kc * 16 + c) * 2;
                ldsm4(qh[kc], a);
                ldsm4(qlf[kc], a + ATILE);
            }
        }

        const uint32_t sK = sb + 2 * ATILE + (uint32_t)(it & 1) * 3 * ATILE;
        const uint32_t sV = sK + 2 * ATILE;

        // ---- S = Q K^T (3-term fp16) ----
        float s[8][4];
        #pragma unroll
        for (int i = 0; i < 8; ++i)
            #pragma unroll
            for (int j = 0; j < 4; ++j) s[i][j] = 0.f;

        #pragma unroll
        for (int nbp = 0; nbp < 4; ++nbp) {
            #pragma unroll
            for (int kc = 0; kc < 4; ++kc) {
                uint32_t kh[4], kl[4];
                const uint32_t a = sK + (uint32_t)(nbp * 16 + k_nr) * SROWB
                                 + (uint32_t)(kc * 16 + k_nc) * 2;
                ldsm4(kh, a);
                ldsm4(kl, a + ATILE);
                mma_f16(s[2*nbp],   qh[kc],  kh[0], kh[1]);
                mma_f16(s[2*nbp],   qlf[kc], kh[0], kh[1]);
                mma_f16(s[2*nbp],   qh[kc],  kl[0], kl[1]);
                mma_f16(s[2*nbp+1], qh[kc],  kh[2], kh[3]);
                mma_f16(s[2*nbp+1], qlf[kc], kh[2], kh[3]);
                mma_f16(s[2*nbp+1], qh[kc],  kl[2], kl[3]);
            }
        }

        // ---- causal mask (diagonal tile only) ----
        if (it == nt) {
            const int rb = (w << 4) + (lane >> 2);
            #pragma unroll
            for (int nb = 0; nb < 8; ++nb) {
                const int c = nb * 8 + ((lane & 3) << 1);
                if (c     > rb)     s[nb][0] = -1e30f;
                if (c + 1 > rb)     s[nb][1] = -1e30f;
                if (c     > rb + 8) s[nb][2] = -1e30f;
                if (c + 1 > rb + 8) s[nb][3] = -1e30f;
            }
        }

        // ---- online softmax (log2 domain), skip rescale if max unchanged ----
        float mt0 = -1e30f, mt1 = -1e30f;
        #pragma unroll
        for (int nb = 0; nb < 8; ++nb) {
            mt0 = fmaxf(mt0, fmaxf(s[nb][0], s[nb][1]));
            mt1 = fmaxf(mt1, fmaxf(s[nb][2], s[nb][3]));
        }
        mt0 = fmaxf(mt0, __shfl_xor_sync(0xffffffffu, mt0, 1));
        mt0 = fmaxf(mt0, __shfl_xor_sync(0xffffffffu, mt0, 2));
        mt1 = fmaxf(mt1, __shfl_xor_sync(0xffffffffu, mt1, 1));
        mt1 = fmaxf(mt1, __shfl_xor_sync(0xffffffffu, mt1, 2));
        if (mt0 > m0 || mt1 > m1) {
            const float mn0 = fmaxf(m0, mt0), mn1 = fmaxf(m1, mt1);
            const float c0 = exp2a(m0 - mn0), c1 = exp2a(m1 - mn1);
            m0 = mn0; m1 = mn1;
            l0 *= c0;  l1 *= c1;
            #pragma unroll
            for (int nb = 0; nb < 8; ++nb) {
                o[nb][0] *= c0; o[nb][1] *= c0; o[nb][2] *= c1; o[nb][3] *= c1;
            }
        }

        uint32_t ph[4][4];
        #pragma unroll
        for (int nb = 0; nb < 8; ++nb) {
            const float p0 = exp2a(s[nb][0] - m0);
            const float p1 = exp2a(s[nb][1] - m0);
            const float p2 = exp2a(s[nb][2] - m1);
            const float p3 = exp2a(s[nb][3] - m1);
            l0 += p0 + p1;  l1 += p2 + p3;
            const int j = nb >> 1, q = (nb & 1) << 1;
            ph[j][q]     = f16x2pk(p0, p1);
            ph[j][q + 1] = f16x2pk(p2, p3);
        }

        // ---- O += Ph Vh (1-term), V^T via ldmatrix.trans ----
        #pragma unroll
        for (int j = 0; j < 4; ++j) {
            #pragma unroll
            for (int nbp = 0; nbp < 4; ++nbp) {
                uint32_t vh[4];
                const uint32_t a = sV + (uint32_t)(j * 16 + v_nr) * SROWB
                                 + (uint32_t)(nbp * 16 + v_nc) * 2;
                ldsm4t(vh, a);
                mma_f16(o[2*nbp],   ph[j], vh[0], vh[1]);
                mma_f16(o[2*nbp+1], ph[j], vh[2], vh[3]);
            }
        }
    }

    // ---- finalize ----
    l0 += __shfl_xor_sync(0xffffffffu, l0, 1);
    l0 += __shfl_xor_sync(0xffffffffu, l0, 2);
    l1 += __shfl_xor_sync(0xffffffffu, l1, 1);
    l1 += __shfl_xor_sync(0xffffffffu, l1, 2);
    const float inv0 = 1.f / l0, inv1 = 1.f / l1;

    const int b = bh >> 4, h = bh & 15;
    const int r0g = q0 + (w << 4) + (lane >> 2);
    #pragma unroll
    for (int nb = 0; nb < 8; ++nb) {
        const int col = h * 64 + nb * 8 + ((lane & 3) << 1);
        {
            const float x0 = o[nb][0] * inv0, x1 = o[nb][1] * inv0;
            const uint32_t hh = bf16x2pk(x0, x1);
            const uint32_t ll = bf16x2pk(x0 - bf_lo(hh), x1 - bf_hi(hh));
            const size_t idx = (size_t)(b * SEQ + r0g) * D_MODEL + col;
            *(uint32_t*)&Oh[idx] = hh;
            *(uint32_t*)&Ol[idx] = ll;
        }
        {
            const float x2 = o[nb][2] * inv1, x3 = o[nb][3] * inv1;
            const uint32_t hh = bf16x2pk(x2, x3);
            const uint32_t ll = bf16x2pk(x2 - bf_lo(hh), x3 - bf_hi(hh));
            const size_t idx = (size_t)(b * SEQ + r0g + 8) * D_MODEL + col;
            *(uint32_t*)&Oh[idx] = hh;
            *(uint32_t*)&Ol[idx] = ll;
        }
    }
}

// ---------------------------------------------------------------------------
extern "C" void kernel_launch(void* const* d_in, const int* in_sizes, int n_in,
                              void* d_out, int out_size)
{
    (void)in_sizes; (void)n_in; (void)out_size;
    const float* x  = (const float*)d_in[0];
    const float* Wq = (const float*)d_in[1];
    const float* bq = (const float*)d_in[2];
    const float* Wk = (const float*)d_in[3];
    const float* bk = (const float*)d_in[4];
    const float* Wv = (const float*)d_in[5];
    const float* bv = (const float*)d_in[6];
    const float* Wo = (const float*)d_in[7];
    const float* bo = (const float*)d_in[8];
    float* out = (float*)d_out;

    __half *Qh, *Ql, *Kh, *Kl, *Vh;
    __nv_bfloat16 *xh, *xl, *Wth, *Wtl, *Oh, *Ol;
    cudaGetSymbolAddress((void**)&Qh,  g_Qh);  cudaGetSymbolAddress((void**)&Ql, g_Ql);
    cudaGetSymbolAddress((void**)&Kh,  g_Kh);  cudaGetSymbolAddress((void**)&Kl, g_Kl);
    cudaGetSymbolAddress((void**)&Vh,  g_Vh);
    cudaGetSymbolAddress((void**)&xh,  g_xh);  cudaGetSymbolAddress((void**)&xl, g_xl);
    cudaGetSymbolAddress((void**)&Wth, g_Wth); cudaGetSymbolAddress((void**)&Wtl, g_Wtl);
    cudaGetSymbolAddress((void**)&Oh,  g_Oh);  cudaGetSymbolAddress((void**)&Ol, g_Ol);

    cudaFuncSetAttribute(gemm_qkv,
                         cudaFuncAttributeMaxDynamicSharedMemorySize, GEMM_SMEM);
    cudaFuncSetAttribute(gemm_out,
                         cudaFuncAttributeMaxDynamicSharedMemorySize, GEMM_SMEM);
    cudaFuncSetAttribute(flash_mma,
                         cudaFuncAttributeMaxDynamicSharedMemorySize, ATT_SMEM);

    const size_t WSZ = (size_t)D_MODEL * D_MODEL;

    convert_split<<<(M_TOTAL * D_MODEL / 4 + 255) / 256, 256>>>(
        x, xh, xl, M_TOTAL * D_MODEL / 4);

    dim3 wtg(32, 32), wtb(32, 8);
    wtrans_split<<<wtg, wtb>>>(Wq, Wth + 0 * WSZ, Wtl + 0 * WSZ);
    wtrans_split<<<wtg, wtb>>>(Wk, Wth + 1 * WSZ, Wtl + 1 * WSZ);
    wtrans_split<<<wtg, wtb>>>(Wv, Wth + 2 * WSZ, Wtl + 2 * WSZ);
    wtrans_split<<<wtg, wtb>>>(Wo, Wth + 3 * WSZ, Wtl + 3 * WSZ);

    dim3 gq(D_MODEL / 128, M_TOTAL / 128, 3);   // fused Q/K/V
    gemm_qkv<<<gq, 256, GEMM_SMEM>>>(xh, xl, Wth, Wtl, bq, bk, bv,
                                     Qh, Ql, Kh, Kl, Vh);

    dim3 ga(SEQ / 64, BATCH * N_HEADS);
    flash_mma<<<ga, 128, ATT_SMEM>>>(Qh, Ql, Kh, Kl, Vh, Oh, Ol);

    dim3 gg(D_MODEL / 128, M_TOTAL / 128);
    gemm_out<<<gg, 256, GEMM_SMEM>>>(Oh, Ol, Wth + 3 * WSZ, Wtl + 3 * WSZ,
                                     bo, out);
}

// round 6
// speedup vs baseline: 3.8135x; 1.0092x over previous
#include <cuda_runtime.h>
#include <cuda_bf16.h>
#include <cuda_fp16.h>
#include <cstdint>

#define D_MODEL  1024
#define N_HEADS  16
#define HEAD_DIM 64
#define BATCH    2
#define SEQ      2048
#define M_TOTAL  (BATCH * SEQ)   // 4096
#define QSCALE   0.18033688011112042f   // 0.125 * log2(e)

// ---------------------------------------------------------------------------
// Device-global scratch (allocation-free rule)
// ---------------------------------------------------------------------------
#define PHSZ (BATCH * N_HEADS * SEQ * HEAD_DIM)   // 4M elems
__device__ __align__(16) __half g_Qh[PHSZ], g_Ql[PHSZ];
__device__ __align__(16) __half g_Kh[PHSZ], g_Kl[PHSZ];
__device__ __align__(16) __half g_Vh[PHSZ];
__device__ __align__(16) __nv_bfloat16 g_xh[M_TOTAL * D_MODEL];
__device__ __align__(16) __nv_bfloat16 g_xl[M_TOTAL * D_MODEL];
__device__ __align__(16) __nv_bfloat16 g_Wth[4 * D_MODEL * D_MODEL]; // W^T hi [N,K]
__device__ __align__(16) __nv_bfloat16 g_Wtl[4 * D_MODEL * D_MODEL]; // W^T lo [N,K]
__device__ __align__(16) __nv_bfloat16 g_Oh[M_TOTAL * D_MODEL];
__device__ __align__(16) __nv_bfloat16 g_Ol[M_TOTAL * D_MODEL];

// ---------------------------------------------------------------------------
// helpers (compute_103-legal: ldmatrix / mma.sync / cp.async / ex2.approx)
// ---------------------------------------------------------------------------
__device__ __forceinline__ uint32_t smem_u32(const void* p) {
    uint32_t a;
    asm("{ .reg .u64 t; cvta.to.shared.u64 t, %1; cvt.u32.u64 %0, t; }"
        : "=r"(a) : "l"(p));
    return a;
}
__device__ __forceinline__ void ldsm4(uint32_t* r, uint32_t addr) {
    asm volatile("ldmatrix.sync.aligned.m8n8.x4.shared.b16 {%0,%1,%2,%3}, [%4];"
        : "=r"(r[0]), "=r"(r[1]), "=r"(r[2]), "=r"(r[3]) : "r"(addr));
}
__device__ __forceinline__ void ldsm4t(uint32_t* r, uint32_t addr) {
    asm volatile("ldmatrix.sync.aligned.m8n8.x4.trans.shared.b16 {%0,%1,%2,%3}, [%4];"
        : "=r"(r[0]), "=r"(r[1]), "=r"(r[2]), "=r"(r[3]) : "r"(addr));
}
__device__ __forceinline__ void mma_bf16(float* c, const uint32_t* a,
                                         uint32_t b0, uint32_t b1) {
    asm volatile(
        "mma.sync.aligned.m16n8k16.row.col.f32.bf16.bf16.f32 "
        "{%0,%1,%2,%3}, {%4,%5,%6,%7}, {%8,%9}, {%0,%1,%2,%3};"
        : "+f"(c[0]), "+f"(c[1]), "+f"(c[2]), "+f"(c[3])
        : "r"(a[0]), "r"(a[1]), "r"(a[2]), "r"(a[3]), "r"(b0), "r"(b1));
}
__device__ __forceinline__ void mma_f16(float* c, const uint32_t* a,
                                        uint32_t b0, uint32_t b1) {
    asm volatile(
        "mma.sync.aligned.m16n8k16.row.col.f32.f16.f16.f32 "
        "{%0,%1,%2,%3}, {%4,%5,%6,%7}, {%8,%9}, {%0,%1,%2,%3};"
        : "+f"(c[0]), "+f"(c[1]), "+f"(c[2]), "+f"(c[3])
        : "r"(a[0]), "r"(a[1]), "r"(a[2]), "r"(a[3]), "r"(b0), "r"(b1));
}
__device__ __forceinline__ float exp2a(float x) {
    float r; asm("ex2.approx.f32 %0, %1;" : "=f"(r) : "f"(x)); return r;
}
__device__ __forceinline__ uint32_t bf16x2pk(float lo, float hi) {
    uint32_t r;
    asm("cvt.rn.bf16x2.f32 %0, %1, %2;" : "=r"(r) : "f"(hi), "f"(lo));
    return r;
}
__device__ __forceinline__ uint32_t f16x2pk(float lo, float hi) {
    uint32_t r;
    asm("cvt.rn.f16x2.f32 %0, %1, %2;" : "=r"(r) : "f"(hi), "f"(lo));
    return r;
}
__device__ __forceinline__ float bf_lo(uint32_t r) { return __uint_as_float(r << 16); }
__device__ __forceinline__ float bf_hi(uint32_t r) { return __uint_as_float(r & 0xffff0000u); }

#define CP16(saddr, gptr) \
    asm volatile("cp.async.cg.shared.global [%0], [%1], 16;" \
        :: "r"(saddr), "l"(gptr) : "memory")
#define CP_COMMIT() asm volatile("cp.async.commit_group;" ::: "memory")
#define CP_WAIT0()  asm volatile("cp.async.wait_group 0;" ::: "memory")
#define CP_WAIT1()  asm volatile("cp.async.wait_group 1;" ::: "memory")

// ---------------------------------------------------------------------------
// Fused prep: z=0 -> x fp32 -> bf16 hi/lo split; z=1..4 -> W transpose+split.
// grid (32, 32, 5), block 256.
// ---------------------------------------------------------------------------
__global__ __launch_bounds__(256) void prep(
    const float* __restrict__ x,
    const float* __restrict__ Wq, const float* __restrict__ Wk,
    const float* __restrict__ Wv, const float* __restrict__ Wo,
    __nv_bfloat16* __restrict__ xh, __nv_bfloat16* __restrict__ xl,
    __nv_bfloat16* __restrict__ Wth, __nv_bfloat16* __restrict__ Wtl)
{
    __shared__ float t[32][33];
    const int z = blockIdx.z;
    const int tid = threadIdx.x;

    if (z == 0) {
        // x split: n4 = 4096*1024/4 = 1048576 float4 groups
        const int bid = blockIdx.y * 32 + blockIdx.x;     // 0..1023
        #pragma unroll
        for (int it = 0; it < 4; ++it) {
            const int i = it * (1024 * 256) + bid * 256 + tid;
            float4 v = ((const float4*)x)[i];
            uint32_t h0 = bf16x2pk(v.x, v.y), h1 = bf16x2pk(v.z, v.w);
            uint32_t l0 = bf16x2pk(v.x - bf_lo(h0), v.y - bf_hi(h0));
            uint32_t l1 = bf16x2pk(v.z - bf_lo(h1), v.w - bf_hi(h1));
            ((uint2*)xh)[i] = make_uint2(h0, h1);
            ((uint2*)xl)[i] = make_uint2(l0, l1);
        }
        return;
    }

    const float* W = (z == 1) ? Wq : (z == 2) ? Wk : (z == 3) ? Wv : Wo;
    const size_t WSZ = (size_t)D_MODEL * D_MODEL;
    __nv_bfloat16* Th = Wth + (size_t)(z - 1) * WSZ;
    __nv_bfloat16* Tl = Wtl + (size_t)(z - 1) * WSZ;

    const int bx = blockIdx.x * 32;   // n block
    const int by = blockIdx.y * 32;   // k block
    const int xx = tid & 31, yy = tid >> 5;   // 32 x 8
    #pragma unroll
    for (int j = 0; j < 32; j += 8)
        t[yy + j][xx] = W[(by + yy + j) * D_MODEL + bx + xx];
    __syncthreads();
    #pragma unroll
    for (int j = 0; j < 32; j += 8) {
        float v = t[xx][yy + j];               // (k=by+xx, n=bx+yy+j)
        __nv_bfloat16 h = __float2bfloat16_rn(v);
        __nv_bfloat16 l = __float2bfloat16_rn(v - __bfloat162float(h));
        Th[(bx + yy + j) * D_MODEL + by + xx] = h;
        Tl[(bx + yy + j) * D_MODEL + by + xx] = l;
    }
}

// ---------------------------------------------------------------------------
// GEMM mainloop: bf16x3 via mma.sync, 128x128 tile, cp.async 2-stage pipeline.
// ---------------------------------------------------------------------------
#define GK     32
#define NKCH   (D_MODEL / GK)        // 32
#define ROW_B  80
#define TILE_B (128 * ROW_B)
#define STG_B  (4 * TILE_B)
#define GEMM_SMEM (2 * STG_B)        // 81920

__device__ __forceinline__ void gemm_core(
    const __nv_bfloat16* __restrict__ Ah, const __nv_bfloat16* __restrict__ Al,
    const __nv_bfloat16* __restrict__ Bh, const __nv_bfloat16* __restrict__ Bl,
    uint32_t sb, int m0, int n0, float acc[4][4][4])
{
    const int tid  = threadIdx.x;
    const int lane = tid & 31;
    const int wid  = tid >> 5;
    const int wm = (wid & 1) * 64;
    const int wn = (wid >> 1) * 32;

    const int lrow = tid >> 1;
    const int lhalf = tid & 1;
    // global pointers: two 16B chunks per tile per thread, at +e0 and +e0+8
    const __nv_bfloat16* pAh = Ah + (size_t)(m0 + lrow) * D_MODEL + lhalf * 16;
    const __nv_bfloat16* pAl = Al + (size_t)(m0 + lrow) * D_MODEL + lhalf * 16;
    const __nv_bfloat16* pBh = Bh + (size_t)(n0 + lrow) * D_MODEL + lhalf * 16;
    const __nv_bfloat16* pBl = Bl + (size_t)(n0 + lrow) * D_MODEL + lhalf * 16;
    const uint32_t w0 = (uint32_t)lrow * ROW_B + (uint32_t)lhalf * 32u;
    const uint32_t w1 = w0 + 16u;

    const uint32_t a_off = (uint32_t)(wm + (lane & 15)) * ROW_B
                         + (uint32_t)(lane >> 4) * 16u;
    const uint32_t b_off = (uint32_t)(wn + ((lane >> 4) << 3) + (lane & 7)) * ROW_B
                         + (uint32_t)((lane >> 3) & 1) * 16u;

    #pragma unroll
    for (int i = 0; i < 4; ++i)
        #pragma unroll
        for (int j = 0; j < 4; ++j)
            #pragma unroll
            for (int r = 0; r < 4; ++r) acc[i][j][r] = 0.f;

    // prologue: chunk 0 -> stage 0
    {
        const uint32_t s = sb;
        CP16(s + w0,              pAh);
        CP16(s + w1,              pAh + 8);
        CP16(s + TILE_B + w0,     pAl);
        CP16(s + TILE_B + w1,     pAl + 8);
        CP16(s + 2 * TILE_B + w0, pBh);
        CP16(s + 2 * TILE_B + w1, pBh + 8);
        CP16(s + 3 * TILE_B + w0, pBl);
        CP16(s + 3 * TILE_B + w1, pBl + 8);
        CP_COMMIT();
    }

    for (int i = 0; i < NKCH; ++i) {
        if (i + 1 < NKCH) {
            const uint32_t s = sb + (uint32_t)((i + 1) & 1) * STG_B;
            const int e = (i + 1) * GK;
            CP16(s + w0,              pAh + e);
            CP16(s + w1,              pAh + e + 8);
            CP16(s + TILE_B + w0,     pAl + e);
            CP16(s + TILE_B + w1,     pAl + e + 8);
            CP16(s + 2 * TILE_B + w0, pBh + e);
            CP16(s + 2 * TILE_B + w1, pBh + e + 8);
            CP16(s + 3 * TILE_B + w0, pBl + e);
            CP16(s + 3 * TILE_B + w1, pBl + e + 8);
            CP_COMMIT();
            CP_WAIT1();              // chunk i landed, chunk i+1 in flight
        } else {
            CP_WAIT0();
        }
        __syncthreads();             // chunk i visible to all warps

        const uint32_t stg = sb + (uint32_t)(i & 1) * STG_B;
        #pragma unroll
        for (int ks = 0; ks < 2; ++ks) {
            uint32_t ah[4][4], al[4][4], bh[2][4], bl[2][4];
            #pragma unroll
            for (int mt = 0; mt < 4; ++mt) {
                ldsm4(ah[mt], stg + a_off + mt * (16 * ROW_B) + ks * 32);
                ldsm4(al[mt], stg + TILE_B + a_off + mt * (16 * ROW_B) + ks * 32);
            }
            #pragma unroll
            for (int ng = 0; ng < 2; ++ng) {
                ldsm4(bh[ng], stg + 2 * TILE_B + b_off + ng * (16 * ROW_B) + ks * 32);
                ldsm4(bl[ng], stg + 3 * TILE_B + b_off + ng * (16 * ROW_B) + ks * 32);
            }
            #pragma unroll
            for (int mt = 0; mt < 4; ++mt)
                #pragma unroll
                for (int n8 = 0; n8 < 4; ++n8) {
                    const int ng = n8 >> 1, hf = (n8 & 1) * 2;
                    mma_bf16(acc[mt][n8], ah[mt], bh[ng][hf], bh[ng][hf + 1]);
                    mma_bf16(acc[mt][n8], al[mt], bh[ng][hf], bh[ng][hf + 1]);
                    mma_bf16(acc[mt][n8], ah[mt], bl[ng][hf], bl[ng][hf + 1]);
                }
        }

        if (i + 1 < NKCH)
            __syncthreads();         // done reading stage i&1 before overwrite
    }
}

// QKV projections fused: grid (8, 32, 3); z: 0=Q, 1=K, 2=V.
__global__ __launch_bounds__(256, 1)
void gemm_qkv(const __nv_bfloat16* __restrict__ xh,
              const __nv_bfloat16* __restrict__ xl,
              const __nv_bfloat16* __restrict__ Wth,
              const __nv_bfloat16* __restrict__ Wtl,
              const float* __restrict__ bq, const float* __restrict__ bk,
              const float* __restrict__ bv,
              __half* __restrict__ Qh, __half* __restrict__ Ql,
              __half* __restrict__ Kh, __half* __restrict__ Kl,
              __half* __restrict__ Vh)
{
    extern __shared__ char smem[];
    const uint32_t sb = smem_u32(smem);
    const int z = blockIdx.z;
    const size_t WSZ = (size_t)D_MODEL * D_MODEL;
    const __nv_bfloat16* Bh = Wth + (size_t)z * WSZ;
    const __nv_bfloat16* Bl = Wtl + (size_t)z * WSZ;
    const float* bias = (z == 0) ? bq : (z == 1) ? bk : bv;
    const float scale = (z == 0) ? QSCALE : 1.0f;
    __half* Ch = (z == 0) ? Qh : (z == 1) ? Kh : Vh;
    __half* Cl = (z == 0) ? Ql : Kl;   // unused for z==2

    const int m0 = blockIdx.y * 128;
    const int n0 = blockIdx.x * 128;

    float acc[4][4][4];
    gemm_core(xh, xl, Bh, Bl, sb, m0, n0, acc);

    const int lane = threadIdx.x & 31;
    const int wid  = threadIdx.x >> 5;
    const int wm = (wid & 1) * 64, wn = (wid >> 1) * 32;
    const int mrow = lane >> 2, ncol = (lane & 3) * 2;
    #pragma unroll
    for (int mt = 0; mt < 4; ++mt) {
        #pragma unroll
        for (int n8 = 0; n8 < 4; ++n8) {
            const int n = n0 + wn + n8 * 8 + ncol;
            const float bx = bias[n], by = bias[n + 1];
            #pragma unroll
            for (int h2 = 0; h2 < 2; ++h2) {
                const int m = m0 + wm + mt * 16 + mrow + h2 * 8;
                const float vx = (acc[mt][n8][h2 * 2 + 0] + bx) * scale;
                const float vy = (acc[mt][n8][h2 * 2 + 1] + by) * scale;
                const int b = m >> 11, s = m & (SEQ - 1);
                const int hh = n >> 6, hd = n & 63;
                const size_t idx =
                    ((size_t)(b * N_HEADS + hh) * SEQ + s) * HEAD_DIM + hd;
                const uint32_t ph = f16x2pk(vx, vy);
                *(uint32_t*)&Ch[idx] = ph;
                if (z != 2) {
                    const __half2 hp = *(const __half2*)&ph;
                    const uint32_t pl = f16x2pk(vx - __half2float(hp.x),
                                                vy - __half2float(hp.y));
                    *(uint32_t*)&Cl[idx] = pl;
                }
            }
        }
    }
}

// Output projection: fp32 out row-major.
__global__ __launch_bounds__(256, 1)
void gemm_out(const __nv_bfloat16* __restrict__ Ah,
              const __nv_bfloat16* __restrict__ Al,
              const __nv_bfloat16* __restrict__ Bh,
              const __nv_bfloat16* __restrict__ Bl,
              const float* __restrict__ bias, float* __restrict__ C)
{
    extern __shared__ char smem[];
    const uint32_t sb = smem_u32(smem);
    const int m0 = blockIdx.y * 128;
    const int n0 = blockIdx.x * 128;

    float acc[4][4][4];
    gemm_core(Ah, Al, Bh, Bl, sb, m0, n0, acc);

    const int lane = threadIdx.x & 31;
    const int wid  = threadIdx.x >> 5;
    const int wm = (wid & 1) * 64, wn = (wid >> 1) * 32;
    const int mrow = lane >> 2, ncol = (lane & 3) * 2;
    #pragma unroll
    for (int mt = 0; mt < 4; ++mt) {
        #pragma unroll
        for (int n8 = 0; n8 < 4; ++n8) {
            const int n = n0 + wn + n8 * 8 + ncol;
            const float bx = bias[n], by = bias[n + 1];
            #pragma unroll
            for (int h2 = 0; h2 < 2; ++h2) {
                const int m = m0 + wm + mt * 16 + mrow + h2 * 8;
                float2 v;
                v.x = acc[mt][n8][h2 * 2 + 0] + bx;
                v.y = acc[mt][n8][h2 * 2 + 1] + by;
                *(float2*)&C[(size_t)m * D_MODEL + n] = v;
            }
        }
    }
}

// ---------------------------------------------------------------------------
// Tensor-core causal flash attention, fp16 operands.
// S = QhKh + QlKh + QhKl (3-term).  O += Ph·Vh (1-term).
// cp.async double-buffered K/V pipeline; skip-rescale on unchanged max.
// ---------------------------------------------------------------------------
#define SROWB 144
#define ATILE (64 * SROWB)               // 9216
#define ATT_SMEM (8 * ATILE)             // 73728

__device__ __forceinline__ void cp_tile3(uint32_t sbase, const __half* gK,
                                         const __half* gKl, const __half* gV,
                                         int tid)
{
    #pragma unroll
    for (int i = 0; i < 4; ++i) {
        const int c = tid + 128 * i;
        const uint32_t sa = (uint32_t)(c >> 3) * SROWB + (uint32_t)(c & 7) * 16u;
        CP16(sbase + sa, gK + 8 * c);
        CP16(sbase + ATILE + sa, gKl + 8 * c);
        CP16(sbase + 2 * ATILE + sa, gV + 8 * c);
    }
}

__global__ __launch_bounds__(128)
void flash_mma(const __half* __restrict__ Qh_, const __half* __restrict__ Ql_,
               const __half* __restrict__ Kh_, const __half* __restrict__ Kl_,
               const __half* __restrict__ Vh_,
               __nv_bfloat16* __restrict__ Oh, __nv_bfloat16* __restrict__ Ol)
{
    extern __shared__ char smem[];
    const uint32_t sb = smem_u32(smem);

    const int tid = threadIdx.x, lane = tid & 31, w = tid >> 5;
    const int bh = blockIdx.y;
    const int qb = gridDim.x - 1 - blockIdx.x;   // long blocks first
    const int q0 = qb * 64;
    const size_t base = (size_t)bh * SEQ * HEAD_DIM;

    // prologue: Q (hi/lo) + K/V stage 0, one cp.async group
    {
        const __half* gQh = Qh_ + base + (size_t)q0 * 64;
        const __half* gQl = Ql_ + base + (size_t)q0 * 64;
        #pragma unroll
        for (int i = 0; i < 4; ++i) {
            const int c = tid + 128 * i;
            const uint32_t sa = (uint32_t)(c >> 3) * SROWB + (uint32_t)(c & 7) * 16u;
            CP16(sb + sa, gQh + 8 * c);
            CP16(sb + ATILE + sa, gQl + 8 * c);
        }
        cp_tile3(sb + 2 * ATILE, Kh_ + base, Kl_ + base, Vh_ + base, tid);
        CP_COMMIT();
    }

    const uint32_t k_nr = (uint32_t)((lane & 7) + ((lane >> 4) << 3));
    const uint32_t k_nc = (uint32_t)(((lane >> 3) & 1) << 3);
    const uint32_t v_nr = (uint32_t)((lane & 7) + (((lane >> 3) & 1) << 3));
    const uint32_t v_nc = (uint32_t)((lane >> 4) << 3);

    uint32_t qh[4][4], qlf[4][4];
    float o[8][4];
    #pragma unroll
    for (int i = 0; i < 8; ++i)
        #pragma unroll
        for (int j = 0; j < 4; ++j) o[i][j] = 0.f;
    float m0 = -1e30f, m1 = -1e30f, l0 = 0.f, l1 = 0.f;

    const int nt = q0 >> 6;
    for (int it = 0; it <= nt; ++it) {
        __syncthreads();              // all warps done reading stage it^1
        if (it < nt) {
            const size_t g = base + (size_t)(it + 1) * 64 * 64;
            cp_tile3(sb + 2 * ATILE + (uint32_t)((it + 1) & 1) * 3 * ATILE,
                     Kh_ + g, Kl_ + g, Vh_ + g, tid);
            CP_COMMIT();
            CP_WAIT1();
        } else {
            CP_WAIT0();
        }
        __syncthreads();

        if (it == 0) {                // Q fragments (once)
            const int r = (w << 4) + (lane & 15);
            const int c = (lane >> 4) << 3;
            #pragma unroll
            for (int kc = 0; kc < 4; ++kc) {
                const uint32_t a = sb + (uint32_t)r * SROWB
                                 + (uint32_t)(kc * 16 + c) * 2;
                ldsm4(qh[kc], a);
                ldsm4(qlf[kc], a + ATILE);
            }
        }

        const uint32_t sK = sb + 2 * ATILE + (uint32_t)(it & 1) * 3 * ATILE;
        const uint32_t sV = sK + 2 * ATILE;

        // ---- S = Q K^T (3-term fp16) ----
        float s[8][4];
        #pragma unroll
        for (int i = 0; i < 8; ++i)
            #pragma unroll
            for (int j = 0; j < 4; ++j) s[i][j] = 0.f;

        #pragma unroll
        for (int nbp = 0; nbp < 4; ++nbp) {
            #pragma unroll
            for (int kc = 0; kc < 4; ++kc) {
                uint32_t kh[4], kl[4];
                const uint32_t a = sK + (uint32_t)(nbp * 16 + k_nr) * SROWB
                                 + (uint32_t)(kc * 16 + k_nc) * 2;
                ldsm4(kh, a);
                ldsm4(kl, a + ATILE);
                mma_f16(s[2*nbp],   qh[kc],  kh[0], kh[1]);
                mma_f16(s[2*nbp],   qlf[kc], kh[0], kh[1]);
                mma_f16(s[2*nbp],   qh[kc],  kl[0], kl[1]);
                mma_f16(s[2*nbp+1], qh[kc],  kh[2], kh[3]);
                mma_f16(s[2*nbp+1], qlf[kc], kh[2], kh[3]);
                mma_f16(s[2*nbp+1], qh[kc],  kl[2], kl[3]);
            }
        }

        // ---- causal mask (diagonal tile only) ----
        if (it == nt) {
            const int rb = (w << 4) + (lane >> 2);
            #pragma unroll
            for (int nb = 0; nb < 8; ++nb) {
                const int c = nb * 8 + ((lane & 3) << 1);
                if (c     > rb)     s[nb][0] = -1e30f;
                if (c + 1 > rb)     s[nb][1] = -1e30f;
                if (c     > rb + 8) s[nb][2] = -1e30f;
                if (c + 1 > rb + 8) s[nb][3] = -1e30f;
            }
        }

        // ---- online softmax (log2 domain), skip rescale if max unchanged ----
        float mt0 = -1e30f, mt1 = -1e30f;
        #pragma unroll
        for (int nb = 0; nb < 8; ++nb) {
            mt0 = fmaxf(mt0, fmaxf(s[nb][0], s[nb][1]));
            mt1 = fmaxf(mt1, fmaxf(s[nb][2], s[nb][3]));
        }
        mt0 = fmaxf(mt0, __shfl_xor_sync(0xffffffffu, mt0, 1));
        mt0 = fmaxf(mt0, __shfl_xor_sync(0xffffffffu, mt0, 2));
        mt1 = fmaxf(mt1, __shfl_xor_sync(0xffffffffu, mt1, 1));
        mt1 = fmaxf(mt1, __shfl_xor_sync(0xffffffffu, mt1, 2));
        if (mt0 > m0 || mt1 > m1) {
            const float mn0 = fmaxf(m0, mt0), mn1 = fmaxf(m1, mt1);
            const float c0 = exp2a(m0 - mn0), c1 = exp2a(m1 - mn1);
            m0 = mn0; m1 = mn1;
            l0 *= c0;  l1 *= c1;
            #pragma unroll
            for (int nb = 0; nb < 8; ++nb) {
                o[nb][0] *= c0; o[nb][1] *= c0; o[nb][2] *= c1; o[nb][3] *= c1;
            }
        }

        uint32_t ph[4][4];
        #pragma unroll
        for (int nb = 0; nb < 8; ++nb) {
            const float p0 = exp2a(s[nb][0] - m0);
            const float p1 = exp2a(s[nb][1] - m0);
            const float p2 = exp2a(s[nb][2] - m1);
            const float p3 = exp2a(s[nb][3] - m1);
            l0 += p0 + p1;  l1 += p2 + p3;
            const int j = nb >> 1, q = (nb & 1) << 1;
            ph[j][q]     = f16x2pk(p0, p1);
            ph[j][q + 1] = f16x2pk(p2, p3);
        }

        // ---- O += Ph Vh ----
        #pragma unroll
        for (int j = 0; j < 4; ++j) {
            #pragma unroll
            for (int nbp = 0; nbp < 4; ++nbp) {
                uint32_t vh[4];
                const uint32_t a = sV + (uint32_t)(j * 16 + v_nr) * SROWB
                                 + (uint32_t)(nbp * 16 + v_nc) * 2;
                ldsm4t(vh, a);
                mma_f16(o[2*nbp],   ph[j], vh[0], vh[1]);
                mma_f16(o[2*nbp+1], ph[j], vh[2], vh[3]);
            }
        }
    }

    // ---- finalize ----
    l0 += __shfl_xor_sync(0xffffffffu, l0, 1);
    l0 += __shfl_xor_sync(0xffffffffu, l0, 2);
    l1 += __shfl_xor_sync(0xffffffffu, l1, 1);
    l1 += __shfl_xor_sync(0xffffffffu, l1, 2);
    const float inv0 = 1.f / l0, inv1 = 1.f / l1;

    const int b = bh >> 4, h = bh & 15;
    const int r0g = q0 + (w << 4) + (lane >> 2);
    #pragma unroll
    for (int nb = 0; nb < 8; ++nb) {
        const int col = h * 64 + nb * 8 + ((lane & 3) << 1);
        {
            const float x0 = o[nb][0] * inv0, x1 = o[nb][1] * inv0;
            const uint32_t hh = bf16x2pk(x0, x1);
            const uint32_t ll = bf16x2pk(x0 - bf_lo(hh), x1 - bf_hi(hh));
            const size_t idx = (size_t)(b * SEQ + r0g) * D_MODEL + col;
            *(uint32_t*)&Oh[idx] = hh;
            *(uint32_t*)&Ol[idx] = ll;
        }
        {
            const float x2 = o[nb][2] * inv1, x3 = o[nb][3] * inv1;
            const uint32_t hh = bf16x2pk(x2, x3);
            const uint32_t ll = bf16x2pk(x2 - bf_lo(hh), x3 - bf_hi(hh));
            const size_t idx = (size_t)(b * SEQ + r0g + 8) * D_MODEL + col;
            *(uint32_t*)&Oh[idx] = hh;
            *(uint32_t*)&Ol[idx] = ll;
        }
    }
}

// ---------------------------------------------------------------------------
extern "C" void kernel_launch(void* const* d_in, const int* in_sizes, int n_in,
                              void* d_out, int out_size)
{
    (void)in_sizes; (void)n_in; (void)out_size;
    const float* x  = (const float*)d_in[0];
    const float* Wq = (const float*)d_in[1];
    const float* bq = (const float*)d_in[2];
    const float* Wk = (const float*)d_in[3];
    const float* bk = (const float*)d_in[4];
    const float* Wv = (const float*)d_in[5];
    const float* bv = (const float*)d_in[6];
    const float* Wo = (const float*)d_in[7];
    const float* bo = (const float*)d_in[8];
    float* out = (float*)d_out;

    __half *Qh, *Ql, *Kh, *Kl, *Vh;
    __nv_bfloat16 *xh, *xl, *Wth, *Wtl, *Oh, *Ol;
    cudaGetSymbolAddress((void**)&Qh,  g_Qh);  cudaGetSymbolAddress((void**)&Ql, g_Ql);
    cudaGetSymbolAddress((void**)&Kh,  g_Kh);  cudaGetSymbolAddress((void**)&Kl, g_Kl);
    cudaGetSymbolAddress((void**)&Vh,  g_Vh);
    cudaGetSymbolAddress((void**)&xh,  g_xh);  cudaGetSymbolAddress((void**)&xl, g_xl);
    cudaGetSymbolAddress((void**)&Wth, g_Wth); cudaGetSymbolAddress((void**)&Wtl, g_Wtl);
    cudaGetSymbolAddress((void**)&Oh,  g_Oh);  cudaGetSymbolAddress((void**)&Ol, g_Ol);

    cudaFuncSetAttribute(gemm_qkv,
                         cudaFuncAttributeMaxDynamicSharedMemorySize, GEMM_SMEM);
    cudaFuncSetAttribute(gemm_out,
                         cudaFuncAttributeMaxDynamicSharedMemorySize, GEMM_SMEM);
    cudaFuncSetAttribute(flash_mma,
                         cudaFuncAttributeMaxDynamicSharedMemorySize, ATT_SMEM);

    const size_t WSZ = (size_t)D_MODEL * D_MODEL;

    // fused prep: x split + 4 weight transposes, one launch
    prep<<<dim3(32, 32, 5), 256>>>(x, Wq, Wk, Wv, Wo, xh, xl, Wth, Wtl);

    dim3 gq(D_MODEL / 128, M_TOTAL / 128, 3);   // fused Q/K/V
    gemm_qkv<<<gq, 256, GEMM_SMEM>>>(xh, xl, Wth, Wtl, bq, bk, bv,
                                     Qh, Ql, Kh, Kl, Vh);

    dim3 ga(SEQ / 64, BATCH * N_HEADS);
    flash_mma<<<ga, 128, ATT_SMEM>>>(Qh, Ql, Kh, Kl, Vh, Oh, Ol);

    dim3 gg(D_MODEL / 128, M_TOTAL / 128);
    gemm_out<<<gg, 256, GEMM_SMEM>>>(Oh, Ol, Wth + 3 * WSZ, Wtl + 3 * WSZ,
                                     bo, out);
}